// round 12
// baseline (speedup 1.0000x reference)
#include <cuda_runtime.h>
#include <cuda_bf16.h>
#include <cstdint>

#define BATCH  2
#define SEQ    4096
#define DMODEL 320
#define HEADS  8
#define DH     40
#define MTOT   (BATCH*SEQ)
#define NBH    (BATCH*HEADS)
#define SCALE  0.15811388300841897f
#define LOG2E  1.4426950408889634f
#define QSCALE (SCALE*LOG2E)
#define NTILE  (SEQ/64)

typedef unsigned long long ull;

// ---- scratch (static device arrays; zero-initialized => padding stays 0) ----
__device__ __nv_bfloat16 g_xh[(size_t)MTOT*DMODEL];
__device__ __nv_bfloat16 g_xl[(size_t)MTOT*DMODEL];
__device__ __nv_bfloat16 g_wh[4][DMODEL*DMODEL];
__device__ __nv_bfloat16 g_wl[4][DMODEL*DMODEL];
__device__ __nv_bfloat16 g_qt[(size_t)NBH*SEQ*48];      // Q*QSCALE bf16, dims 40..47 = 0
__device__ uint32_t      g_kf[(size_t)NBH*NTILE*1536];  // K bf16 frag: t01 uint4 | t2 uint2
__device__ __nv_bfloat16 g_vh[(size_t)NBH*DH*SEQ];      // V hi bf16 [bh][d][s]
__device__ float         g_part[64][DMODEL];            // per-m-block exact V colsums
__device__ __nv_bfloat16 g_aoh[(size_t)MTOT*DMODEL];
__device__ __nv_bfloat16 g_aol[(size_t)MTOT*DMODEL];

// ---- helpers ----
__device__ __forceinline__ float ex2f(float x) {
    float y; asm("ex2.approx.ftz.f32 %0, %1;" : "=f"(y) : "f"(x)); return y;
}
__device__ __forceinline__ uint32_t bf16x2(float hi, float lo) {
    uint32_t r; asm("cvt.rn.bf16x2.f32 %0, %1, %2;" : "=r"(r) : "f"(hi), "f"(lo)); return r;
}
__device__ __forceinline__ uint32_t smem_u32(const void* p) {
    uint32_t a;
    asm("{ .reg .u64 t; cvta.to.shared.u64 t, %1; cvt.u32.u64 %0, t; }" : "=r"(a) : "l"(p));
    return a;
}
__device__ __forceinline__ void mma_bf16(float* c, uint32_t a0, uint32_t a1,
                                         uint32_t a2, uint32_t a3, uint32_t b0, uint32_t b1) {
    asm volatile("mma.sync.aligned.m16n8k16.row.col.f32.bf16.bf16.f32 "
        "{%0,%1,%2,%3}, {%4,%5,%6,%7}, {%8,%9}, {%0,%1,%2,%3};"
        : "+f"(c[0]), "+f"(c[1]), "+f"(c[2]), "+f"(c[3])
        : "r"(a0), "r"(a1), "r"(a2), "r"(a3), "r"(b0), "r"(b1));
}
__device__ __forceinline__ void ldm4(uint32_t* r, uint32_t addr) {
    asm volatile("ldmatrix.sync.aligned.m8n8.x4.shared.b16 {%0,%1,%2,%3}, [%4];"
        : "=r"(r[0]), "=r"(r[1]), "=r"(r[2]), "=r"(r[3]) : "r"(addr));
}
__device__ __forceinline__ void ldm2(uint32_t* r, uint32_t addr) {
    asm volatile("ldmatrix.sync.aligned.m8n8.x2.shared.b16 {%0,%1}, [%2];"
        : "=r"(r[0]), "=r"(r[1]) : "r"(addr));
}
#define CP16(s, g) asm volatile("cp.async.ca.shared.global [%0], [%1], 16;" :: "r"(s), "l"(g))
#define CP_COMMIT() asm volatile("cp.async.commit_group;" ::: "memory")
#define CP_WAIT(n)  asm volatile("cp.async.wait_group %0;" :: "n"(n) : "memory")

// ---------------------------------------------------------------------------
// fp32 -> bf16 hi/lo splits
// ---------------------------------------------------------------------------
__global__ void __launch_bounds__(256) split_kernel(
    const float* __restrict__ in, __nv_bfloat16* __restrict__ h,
    __nv_bfloat16* __restrict__ l, int n4)
{
    int i = blockIdx.x * 256 + threadIdx.x;
    if (i >= n4) return;
    float4 v = ((const float4*)in)[i];
    __nv_bfloat16 h0 = __float2bfloat16(v.x), h1 = __float2bfloat16(v.y);
    __nv_bfloat16 h2 = __float2bfloat16(v.z), h3 = __float2bfloat16(v.w);
    ((__nv_bfloat162*)h)[2*i]   = __nv_bfloat162(h0, h1);
    ((__nv_bfloat162*)h)[2*i+1] = __nv_bfloat162(h2, h3);
    ((__nv_bfloat162*)l)[2*i]   = __nv_bfloat162(
        __float2bfloat16(v.x - __bfloat162float(h0)),
        __float2bfloat16(v.y - __bfloat162float(h1)));
    ((__nv_bfloat162*)l)[2*i+1] = __nv_bfloat162(
        __float2bfloat16(v.z - __bfloat162float(h2)),
        __float2bfloat16(v.w - __bfloat162float(h3)));
}

__global__ void __launch_bounds__(256) wsplit_kernel(
    const float* __restrict__ w0, const float* __restrict__ w1,
    const float* __restrict__ w2, const float* __restrict__ w3,
    __nv_bfloat16* __restrict__ h, __nv_bfloat16* __restrict__ l)
{
    const int mat = blockIdx.y;
    const float* in = (mat == 0) ? w0 : (mat == 1) ? w1 : (mat == 2) ? w2 : w3;
    int i = blockIdx.x * 256 + threadIdx.x;
    const int n4 = DMODEL * DMODEL / 4;
    if (i >= n4) return;
    float4 v = ((const float4*)in)[i];
    size_t o = (size_t)mat * (DMODEL * DMODEL / 2) + 2 * i;
    __nv_bfloat16 h0 = __float2bfloat16(v.x), h1 = __float2bfloat16(v.y);
    __nv_bfloat16 h2 = __float2bfloat16(v.z), h3 = __float2bfloat16(v.w);
    ((__nv_bfloat162*)h)[o]   = __nv_bfloat162(h0, h1);
    ((__nv_bfloat162*)h)[o+1] = __nv_bfloat162(h2, h3);
    ((__nv_bfloat162*)l)[o]   = __nv_bfloat162(
        __float2bfloat16(v.x - __bfloat162float(h0)),
        __float2bfloat16(v.y - __bfloat162float(h1)));
    ((__nv_bfloat162*)l)[o+1] = __nv_bfloat162(
        __float2bfloat16(v.z - __bfloat162float(h2)),
        __float2bfloat16(v.w - __bfloat162float(h3)));
}

// ---------------------------------------------------------------------------
// GEMM core: BM=128 BN=64 BK=32, 256 thr, 3-stage cp.async, ONE sync per step.
// ---------------------------------------------------------------------------
#define ST_BYTES 30720

struct GemmCore {
    const char* gb[6];
    uint32_t so[6];
    uint32_t a_fb, b_fb;
    float acc[2][4][4];
};

__device__ __forceinline__ void gemm_setup(
    GemmCore& g, int tid, int lane, int wm, int wn, int m0, int n0,
    const __nv_bfloat16* Ah, const __nv_bfloat16* Al,
    const __nv_bfloat16* Wh, const __nv_bfloat16* Wl)
{
    constexpr int K = DMODEL;
    #pragma unroll
    for (int j = 0; j < 6; j++) {
        int c = tid + j * 256;
        if (c < 1024) {
            int split = c >> 9, cc = c & 511, row = cc >> 2, col = cc & 3;
            g.gb[j] = (const char*)((split ? Al : Ah) + (size_t)(m0 + row) * K) + col * 16;
            g.so[j] = split * 10240 + row * 80 + col * 16;
        } else {
            int cc = c - 1024, split = cc >> 8;
            cc &= 255; int row = cc >> 2, col = cc & 3;
            g.gb[j] = (const char*)((split ? Wl : Wh) + (size_t)(n0 + row) * K) + col * 16;
            g.so[j] = 20480 + split * 5120 + row * 80 + col * 16;
        }
    }
    g.a_fb = (wm * 32 + (lane & 15)) * 80 + (lane >> 4) * 16;
    g.b_fb = 20480 + (wn * 32 + (lane & 15)) * 80 + (lane >> 4) * 16;
    #pragma unroll
    for (int mt = 0; mt < 2; mt++)
        #pragma unroll
        for (int nt = 0; nt < 4; nt++)
            #pragma unroll
            for (int i = 0; i < 4; i++) g.acc[mt][nt][i] = 0.f;
}

__device__ __forceinline__ void gemm_main(GemmCore& g, uint32_t sb) {
    constexpr int NKT = DMODEL / 32;   // 10
    #pragma unroll
    for (int p = 0; p < 2; p++) {
        #pragma unroll
        for (int j = 0; j < 6; j++)
            CP16(sb + p * ST_BYTES + g.so[j], g.gb[j] + p * 64);
        CP_COMMIT();
    }

    for (int kt = 0; kt < NKT; kt++) {
        CP_WAIT(1);
        __syncthreads();
        {
            int pre = kt + 2;
            if (pre < NKT) {
                uint32_t stb = sb + (pre % 3) * ST_BYTES;
                #pragma unroll
                for (int j = 0; j < 6; j++)
                    CP16(stb + g.so[j], g.gb[j] + pre * 64);
            }
            CP_COMMIT();
        }

        const uint32_t ah_b = sb + (kt % 3) * ST_BYTES + g.a_fb;
        const uint32_t bh_b = sb + (kt % 3) * ST_BYTES + g.b_fb;
        #pragma unroll
        for (int kk = 0; kk < 2; kk++) {
            uint32_t ah[2][4], al[2][4], bh[2][4], bl[2][4];
            ldm4(ah[0], ah_b + kk * 32);
            ldm4(ah[1], ah_b + 1280 + kk * 32);
            ldm4(al[0], ah_b + 10240 + kk * 32);
            ldm4(al[1], ah_b + 11520 + kk * 32);
            ldm4(bh[0], bh_b + kk * 32);
            ldm4(bh[1], bh_b + 1280 + kk * 32);
            ldm4(bl[0], bh_b + 5120 + kk * 32);
            ldm4(bl[1], bh_b + 6400 + kk * 32);
            #pragma unroll
            for (int mt = 0; mt < 2; mt++)
                #pragma unroll
                for (int gg = 0; gg < 2; gg++)
                    #pragma unroll
                    for (int s = 0; s < 2; s++) {
                        float* c = g.acc[mt][gg * 2 + s];
                        mma_bf16(c, ah[mt][0], ah[mt][1], ah[mt][2], ah[mt][3],
                                 bh[gg][s], bh[gg][s + 2]);
                        mma_bf16(c, ah[mt][0], ah[mt][1], ah[mt][2], ah[mt][3],
                                 bl[gg][s], bl[gg][s + 2]);
                        mma_bf16(c, al[mt][0], al[mt][1], al[mt][2], al[mt][3],
                                 bh[gg][s], bh[gg][s + 2]);
                    }
        }
    }
}

// ---------------------------------------------------------------------------
// Fused QKV projection: blockIdx.z = 0:Q(bf16), 1:K(bf16 frag), 2:V(hi+colsum)
// ---------------------------------------------------------------------------
__global__ void __launch_bounds__(256) gemm_qkv(
    const __nv_bfloat16* __restrict__ Ah, const __nv_bfloat16* __restrict__ Al,
    const __nv_bfloat16* __restrict__ Whb, const __nv_bfloat16* __restrict__ Wlb,
    __nv_bfloat16* __restrict__ Qt, uint32_t* __restrict__ Kf,
    __nv_bfloat16* __restrict__ Vh, float* __restrict__ Part)
{
    extern __shared__ __align__(16) char sm[];
    const int tid = threadIdx.x, lane = tid & 31, w = tid >> 5;
    const int wm = w & 3, wn = w >> 2;
    const int m0 = blockIdx.y * 128, n0 = blockIdx.x * 64;
    const int mode = blockIdx.z;
    const uint32_t sb = smem_u32(sm);

    GemmCore g;
    gemm_setup(g, tid, lane, wm, wn, m0, n0,
               Ah, Al, Whb + (size_t)mode * DMODEL * DMODEL,
               Wlb + (size_t)mode * DMODEL * DMODEL);
    gemm_main(g, sb);

    const int r = lane >> 2, c2 = (lane & 3) * 2;
    #pragma unroll
    for (int mt = 0; mt < 2; mt++) {
        #pragma unroll
        for (int i = 0; i < 2; i++) {
            int m = m0 + wm * 32 + mt * 16 + r + i * 8;
            int b = m >> 12, s = m & (SEQ - 1);
            #pragma unroll
            for (int nt = 0; nt < 4; nt++) {
                float v0 = g.acc[mt][nt][i * 2], v1 = g.acc[mt][nt][i * 2 + 1];
                int n = n0 + wn * 32 + nt * 8 + c2;    // even
                int hd = n / DH, d = n - hd * DH;
                int bh = b * HEADS + hd;
                if (mode == 0) {
                    // Q bf16 [bh][s][48], dims 40..47 never written (zero-init)
                    *(uint32_t*)&Qt[((size_t)bh * SEQ + s) * 48 + d] =
                        bf16x2(v1 * QSCALE, v0 * QSCALE);
                } else if (mode == 1) {
                    // K frag: t0/t1 packed as uint4 at (nn*4+c)*4 + t*2 + reg,
                    //         t2 as uint2 at 1024 + (nn*4+c)*2 + reg
                    int tile = s >> 6, nn = s & 63;
                    int t = d >> 4, rem = d & 15;
                    int reg = rem >> 3, c = (rem >> 1) & 3;
                    size_t base = (size_t)(bh * NTILE + tile) * 1536;
                    if (t < 2)
                        Kf[base + ((nn * 4 + c) << 2) + t * 2 + reg] = bf16x2(v1, v0);
                    else
                        Kf[base + 1024 + ((nn * 4 + c) << 1) + reg] = bf16x2(v1, v0);
                } else {
                    size_t o = ((size_t)bh * DH + d) * SEQ + s;
                    Vh[o]       = __float2bfloat16(v0);
                    Vh[o + SEQ] = __float2bfloat16(v1);
                }
            }
        }
    }

    // exact V column sums (mode 2): per-block partials, no atomics
    if (mode == 2) {
        __syncthreads();
        float* red = (float*)sm;         // [4][64]
        #pragma unroll
        for (int nt = 0; nt < 4; nt++) {
            float s0 = g.acc[0][nt][0] + g.acc[0][nt][2] + g.acc[1][nt][0] + g.acc[1][nt][2];
            float s1 = g.acc[0][nt][1] + g.acc[0][nt][3] + g.acc[1][nt][1] + g.acc[1][nt][3];
            #pragma unroll
            for (int msk = 4; msk <= 16; msk <<= 1) {
                s0 += __shfl_xor_sync(0xFFFFFFFFu, s0, msk);
                s1 += __shfl_xor_sync(0xFFFFFFFFu, s1, msk);
            }
            if (r == 0) {
                int col = wn * 32 + nt * 8 + c2;
                red[wm * 64 + col]     = s0;
                red[wm * 64 + col + 1] = s1;
            }
        }
        __syncthreads();
        if (tid < 64) {
            Part[(size_t)blockIdx.y * DMODEL + blockIdx.x * 64 + tid] =
                red[tid] + red[64 + tid] + red[128 + tid] + red[192 + tid];
        }
    }
}

// ---------------------------------------------------------------------------
// Out projection (fp32 + bias)
// ---------------------------------------------------------------------------
__global__ void __launch_bounds__(256) gemm_out(
    const __nv_bfloat16* __restrict__ Ah, const __nv_bfloat16* __restrict__ Al,
    const __nv_bfloat16* __restrict__ Wh, const __nv_bfloat16* __restrict__ Wl,
    const float* __restrict__ bias, float* __restrict__ Cf)
{
    extern __shared__ __align__(16) char sm[];
    const int tid = threadIdx.x, lane = tid & 31, w = tid >> 5;
    const int wm = w & 3, wn = w >> 2;
    const int m0 = blockIdx.y * 128, n0 = blockIdx.x * 64;
    const uint32_t sb = smem_u32(sm);

    GemmCore g;
    gemm_setup(g, tid, lane, wm, wn, m0, n0, Ah, Al, Wh, Wl);
    gemm_main(g, sb);

    const int r = lane >> 2, c2 = (lane & 3) * 2;
    #pragma unroll
    for (int mt = 0; mt < 2; mt++) {
        #pragma unroll
        for (int i = 0; i < 2; i++) {
            int m = m0 + wm * 32 + mt * 16 + r + i * 8;
            #pragma unroll
            for (int nt = 0; nt < 4; nt++) {
                int n = n0 + wn * 32 + nt * 8 + c2;
                float2 u = make_float2(g.acc[mt][nt][i*2] + bias[n],
                                       g.acc[mt][nt][i*2+1] + bias[n+1]);
                *(float2*)&Cf[(size_t)m * DMODEL + n] = u;
            }
        }
    }
}

// ---------------------------------------------------------------------------
// Flash attention: bf16 MMA1 (vectorized K-frag loads) + bf16 MMA2 (V hi).
// ---------------------------------------------------------------------------
#define KT_BYTES 6144
#define VROW     144
#define VT_BYTES (DH * VROW)                    // 5760
#define STAGE_BYTES (KT_BYTES + VT_BYTES)       // 11904
#define SM_ATTN (4 * STAGE_BYTES)               // 47616

__global__ void __launch_bounds__(256, 2) attn_kernel(
    const __nv_bfloat16* __restrict__ Qg, const char* __restrict__ Kf,
    const char* __restrict__ Vh, const float* __restrict__ Part,
    __nv_bfloat16* __restrict__ aoh, __nv_bfloat16* __restrict__ aol)
{
    extern __shared__ __align__(16) char smem[];
    __shared__ float cs_s[DH];
    const uint32_t sb = smem_u32(smem);
    const int tid = threadIdx.x, w = tid >> 5, lane = tid & 31;
    const int r4 = lane >> 2, c4 = lane & 3;
    const int bh = blockIdx.y, bB = bh >> 3, hh = bh & 7;
    const int q0 = blockIdx.x * 128;

    // cp.async chunks: K 384 + V 320 = 704 per tile; 3 per thread (3rd partial)
    const char* src[3]; uint32_t doff[3]; int adv[3];
    const bool ok2 = tid < 192;
    #pragma unroll
    for (int j = 0; j < 3; j++) {
        int cid = tid + j * 256;
        if (cid < 384) {
            src[j]  = Kf + (size_t)bh * (NTILE * KT_BYTES) + cid * 16;
            adv[j]  = KT_BYTES;
            doff[j] = cid * 16;
        } else if (cid < 704) {
            int v = cid - 384;
            int d = v >> 3, col = (v & 7) * 16;
            src[j]  = Vh + (((size_t)bh * DH + d) * SEQ) * 2 + col;
            adv[j]  = 128;
            doff[j] = KT_BYTES + d * VROW + col;
        } else {
            src[j] = nullptr; adv[j] = 0; doff[j] = 0;
        }
    }

    // prologue: prefetch 3 tiles
    #pragma unroll
    for (int p = 0; p < 3; p++) {
        #pragma unroll
        for (int j = 0; j < 2; j++)
            CP16(sb + p * STAGE_BYTES + doff[j], src[j] + (size_t)p * adv[j]);
        if (ok2) CP16(sb + p * STAGE_BYTES + doff[2], src[2] + (size_t)p * adv[2]);
        CP_COMMIT();
    }

    // exact V colsums for this (bh): reduce Part rows bB*32..bB*32+31
    if (tid < DH) {
        const float* pp = Part + (size_t)(bB * 32) * DMODEL + hh * DH + tid;
        float s = 0.f;
        #pragma unroll
        for (int j = 0; j < 32; j++) s += pp[(size_t)j * DMODEL];
        cs_s[tid] = s;
    }

    // Q A-fragments (bf16, resident; dims 40..47 read from zero-init padding)
    const __nv_bfloat16* Qb = Qg + ((size_t)bh * SEQ + q0) * 48;
    uint32_t qa[3][4];
    {
        const int R = 16 * w + r4;
        #pragma unroll
        for (int t = 0; t < 3; t++) {
            int k0 = 16 * t + 2 * c4;
            qa[t][0] = *(const uint32_t*)(Qb + (size_t)R * 48 + k0);
            qa[t][1] = *(const uint32_t*)(Qb + (size_t)(R + 8) * 48 + k0);
            qa[t][2] = *(const uint32_t*)(Qb + (size_t)R * 48 + k0 + 8);
            qa[t][3] = *(const uint32_t*)(Qb + (size_t)(R + 8) * 48 + k0 + 8);
        }
    }

    const uint32_t vl01 = ((lane & 7) + ((lane >> 4) << 3)) * VROW + ((lane >> 3) & 1) * 16;
    const uint32_t vl4  = (lane & 7) * VROW + ((lane >> 3) & 1) * 16;

    float o[5][4];
    #pragma unroll
    for (int b = 0; b < 5; b++) { o[b][0]=0.f; o[b][1]=0.f; o[b][2]=0.f; o[b][3]=0.f; }
    float l0a = 0.f, l0b = 0.f, l1a = 0.f, l1b = 0.f;

    for (int i = 0; i < NTILE; i++) {
        CP_WAIT(2);
        __syncthreads();

        {
            int pre = i + 3;
            if (pre < NTILE) {
                uint32_t stb = sb + (pre & 3) * STAGE_BYTES;
                #pragma unroll
                for (int j = 0; j < 2; j++)
                    CP16(stb + doff[j], src[j] + (size_t)pre * adv[j]);
                if (ok2) CP16(stb + doff[2], src[2] + (size_t)pre * adv[2]);
            }
            CP_COMMIT();
        }

        const int cur = i & 3;
        const uint4* kf4  = (const uint4*)(smem + cur * STAGE_BYTES);
        const uint2* kf2t = (const uint2*)(smem + cur * STAGE_BYTES + 4096);

        // MMA1: S = Q K^T — t0/t1 via LDS.128 (batched 4), t2 via LDS.64
        float s[8][4];
        #pragma unroll
        for (int b = 0; b < 8; b++) { s[b][0]=0.f; s[b][1]=0.f; s[b][2]=0.f; s[b][3]=0.f; }
        #pragma unroll
        for (int gq = 0; gq < 2; gq++) {
            uint4 kkA[4];
            #pragma unroll
            for (int b = 0; b < 4; b++)
                kkA[b] = kf4[((8 * (4 * gq + b) + r4) * 4 + c4)];
            #pragma unroll
            for (int b = 0; b < 4; b++)
                mma_bf16(s[4*gq+b], qa[0][0], qa[0][1], qa[0][2], qa[0][3],
                         kkA[b].x, kkA[b].y);
            #pragma unroll
            for (int b = 0; b < 4; b++)
                mma_bf16(s[4*gq+b], qa[1][0], qa[1][1], qa[1][2], qa[1][3],
                         kkA[b].z, kkA[b].w);
        }
        {
            uint2 kkB[8];
            #pragma unroll
            for (int b = 0; b < 8; b++)
                kkB[b] = kf2t[(8 * b + r4) * 4 + c4];
            #pragma unroll
            for (int b = 0; b < 8; b++)
                mma_bf16(s[b], qa[2][0], qa[2][1], qa[2][2], qa[2][3],
                         kkB[b].x, kkB[b].y);
        }

        // softmax
        uint32_t pb[8][2];
        #pragma unroll
        for (int b = 0; b < 8; b++) {
            float p0 = ex2f(s[b][0]), p1 = ex2f(s[b][1]);
            float p2 = ex2f(s[b][2]), p3 = ex2f(s[b][3]);
            l0a += p0; l0b += p1; l1a += p2; l1b += p3;
            pb[b][0] = bf16x2(p1 - 1.f, p0 - 1.f);
            pb[b][1] = bf16x2(p3 - 1.f, p2 - 1.f);
        }

        // MMA2: O += (P-1) * Vh
        const uint32_t vbase = sb + cur * STAGE_BYTES + KT_BYTES;
        #pragma unroll
        for (int t = 0; t < 4; t++) {
            uint32_t a0 = pb[2*t][0],   a1 = pb[2*t][1];
            uint32_t a2 = pb[2*t+1][0], a3 = pb[2*t+1][1];
            uint32_t f[10];
            uint32_t hb0 = vbase + 32 * t;
            ldm4(f,     hb0 + vl01);
            ldm4(f + 4, hb0 + 16 * VROW + vl01);
            ldm2(f + 8, hb0 + 32 * VROW + vl4);
            #pragma unroll
            for (int b = 0; b < 5; b++)
                mma_bf16(o[b], a0, a1, a2, a3, f[2*b], f[2*b+1]);
        }
    }

    float l0 = l0a + l0b, l1 = l1a + l1b;
    l0 += __shfl_xor_sync(0xFFFFFFFFu, l0, 1);
    l0 += __shfl_xor_sync(0xFFFFFFFFu, l0, 2);
    l1 += __shfl_xor_sync(0xFFFFFFFFu, l1, 1);
    l1 += __shfl_xor_sync(0xFFFFFFFFu, l1, 2);
    const float inv0 = 1.f / l0, inv1 = 1.f / l1;

    const size_t base0 = ((size_t)bB * SEQ + q0 + 16 * w + r4) * DMODEL + hh * DH;
    const size_t base1 = base0 + (size_t)8 * DMODEL;
    #pragma unroll
    for (int b = 0; b < 5; b++) {
        int d0 = 8 * b + 2 * c4;
        float cs0 = cs_s[d0], cs1 = cs_s[d0 + 1];
        float u0 = (o[b][0] + cs0) * inv0;
        float u1 = (o[b][1] + cs1) * inv0;
        __nv_bfloat16 h0 = __float2bfloat16(u0), h1 = __float2bfloat16(u1);
        *(__nv_bfloat162*)&aoh[base0 + d0] = __nv_bfloat162(h0, h1);
        *(__nv_bfloat162*)&aol[base0 + d0] = __nv_bfloat162(
            __float2bfloat16(u0 - __bfloat162float(h0)),
            __float2bfloat16(u1 - __bfloat162float(h1)));
        float w0 = (o[b][2] + cs0) * inv1;
        float w1 = (o[b][3] + cs1) * inv1;
        __nv_bfloat16 g0 = __float2bfloat16(w0), g1 = __float2bfloat16(w1);
        *(__nv_bfloat162*)&aoh[base1 + d0] = __nv_bfloat162(g0, g1);
        *(__nv_bfloat162*)&aol[base1 + d0] = __nv_bfloat162(
            __float2bfloat16(w0 - __bfloat162float(g0)),
            __float2bfloat16(w1 - __bfloat162float(g1)));
    }
}

// ---------------------------------------------------------------------------
extern "C" void kernel_launch(void* const* d_in, const int* in_sizes, int n_in,
                              void* d_out, int out_size)
{
    const float* x    = (const float*)d_in[0];
    const float* Wq   = (const float*)d_in[1];
    const float* Wk   = (const float*)d_in[2];
    const float* Wv   = (const float*)d_in[3];
    const float* Wout = (const float*)d_in[4];
    const float* bout = (const float*)d_in[5];
    float* out = (float*)d_out;

    __nv_bfloat16 *xh, *xl, *whp, *wlp, *vh, *aoh, *aol, *qt;
    uint32_t* kf;
    float *part;
    cudaGetSymbolAddress((void**)&xh,   g_xh);
    cudaGetSymbolAddress((void**)&xl,   g_xl);
    cudaGetSymbolAddress((void**)&whp,  g_wh);
    cudaGetSymbolAddress((void**)&wlp,  g_wl);
    cudaGetSymbolAddress((void**)&qt,   g_qt);
    cudaGetSymbolAddress((void**)&kf,   g_kf);
    cudaGetSymbolAddress((void**)&vh,   g_vh);
    cudaGetSymbolAddress((void**)&part, g_part);
    cudaGetSymbolAddress((void**)&aoh,  g_aoh);
    cudaGetSymbolAddress((void**)&aol,  g_aol);

    const int WSZ = DMODEL * DMODEL;
    cudaFuncSetAttribute(gemm_qkv, cudaFuncAttributeMaxDynamicSharedMemorySize, 3*ST_BYTES);
    cudaFuncSetAttribute(gemm_out, cudaFuncAttributeMaxDynamicSharedMemorySize, 3*ST_BYTES);
    cudaFuncSetAttribute(attn_kernel, cudaFuncAttributeMaxDynamicSharedMemorySize, SM_ATTN);

    split_kernel<<<(MTOT*DMODEL/4 + 255)/256, 256>>>(x, xh, xl, MTOT*DMODEL/4);
    dim3 gws((WSZ/4 + 255)/256, 4);
    wsplit_kernel<<<gws, 256>>>(Wq, Wk, Wv, Wout, whp, wlp);

    dim3 gqkv(DMODEL / 64, MTOT / 128, 3);   // (5, 64, 3)
    gemm_qkv<<<gqkv, 256, 3*ST_BYTES>>>(xh, xl, whp, wlp, qt, kf, vh, part);

    dim3 gattn(SEQ / 128, NBH);              // (32, 16)
    attn_kernel<<<gattn, 256, SM_ATTN>>>(qt, (const char*)kf, (const char*)vh,
                                         part, aoh, aol);

    dim3 gout(DMODEL / 64, MTOT / 128);      // (5, 64)
    gemm_out<<<gout, 256, 3*ST_BYTES>>>(aoh, aol, whp + 3*WSZ, wlp + 3*WSZ,
                                        bout, out);
}

// round 13
// speedup vs baseline: 1.0502x; 1.0502x over previous
#include <cuda_runtime.h>
#include <cuda_bf16.h>
#include <cstdint>

#define BATCH  2
#define SEQ    4096
#define DMODEL 320
#define HEADS  8
#define DH     40
#define MTOT   (BATCH*SEQ)
#define NBH    (BATCH*HEADS)
#define SCALE  0.15811388300841897f
#define LOG2E  1.4426950408889634f
#define QSCALE (SCALE*LOG2E)
#define NTILE  (SEQ/64)

typedef unsigned long long ull;

// ---- scratch (static device arrays; zero-initialized => padding stays 0) ----
__device__ __nv_bfloat16 g_xh[(size_t)MTOT*DMODEL];
__device__ __nv_bfloat16 g_xl[(size_t)MTOT*DMODEL];
__device__ __nv_bfloat16 g_wh[4][DMODEL*DMODEL];
__device__ __nv_bfloat16 g_wl[4][DMODEL*DMODEL];
__device__ __nv_bfloat16 g_qt[(size_t)NBH*SEQ*48];      // Q*QSCALE bf16, dims 40..47 = 0
__device__ uint32_t      g_kf[(size_t)NBH*NTILE*1536];  // K bf16 frag: t01 uint4 | t2 uint2
__device__ __nv_bfloat16 g_vh[(size_t)NBH*DH*SEQ];      // V hi bf16 [bh][d][s]
__device__ float         g_part[64][DMODEL];            // per-m-block exact V colsums
__device__ __nv_bfloat16 g_aoh[(size_t)MTOT*DMODEL];
__device__ __nv_bfloat16 g_aol[(size_t)MTOT*DMODEL];

// ---- helpers ----
__device__ __forceinline__ float ex2f(float x) {
    float y; asm("ex2.approx.ftz.f32 %0, %1;" : "=f"(y) : "f"(x)); return y;
}
__device__ __forceinline__ uint32_t bf16x2(float hi, float lo) {
    uint32_t r; asm("cvt.rn.bf16x2.f32 %0, %1, %2;" : "=r"(r) : "f"(hi), "f"(lo)); return r;
}
__device__ __forceinline__ uint32_t smem_u32(const void* p) {
    uint32_t a;
    asm("{ .reg .u64 t; cvta.to.shared.u64 t, %1; cvt.u32.u64 %0, t; }" : "=r"(a) : "l"(p));
    return a;
}
__device__ __forceinline__ void mma_bf16(float* c, uint32_t a0, uint32_t a1,
                                         uint32_t a2, uint32_t a3, uint32_t b0, uint32_t b1) {
    asm volatile("mma.sync.aligned.m16n8k16.row.col.f32.bf16.bf16.f32 "
        "{%0,%1,%2,%3}, {%4,%5,%6,%7}, {%8,%9}, {%0,%1,%2,%3};"
        : "+f"(c[0]), "+f"(c[1]), "+f"(c[2]), "+f"(c[3])
        : "r"(a0), "r"(a1), "r"(a2), "r"(a3), "r"(b0), "r"(b1));
}
__device__ __forceinline__ void ldm4(uint32_t* r, uint32_t addr) {
    asm volatile("ldmatrix.sync.aligned.m8n8.x4.shared.b16 {%0,%1,%2,%3}, [%4];"
        : "=r"(r[0]), "=r"(r[1]), "=r"(r[2]), "=r"(r[3]) : "r"(addr));
}
__device__ __forceinline__ void ldm2(uint32_t* r, uint32_t addr) {
    asm volatile("ldmatrix.sync.aligned.m8n8.x2.shared.b16 {%0,%1}, [%2];"
        : "=r"(r[0]), "=r"(r[1]) : "r"(addr));
}
#define CP16(s, g) asm volatile("cp.async.ca.shared.global [%0], [%1], 16;" :: "r"(s), "l"(g))
#define CP_COMMIT() asm volatile("cp.async.commit_group;" ::: "memory")
#define CP_WAIT(n)  asm volatile("cp.async.wait_group %0;" :: "n"(n) : "memory")

// ---------------------------------------------------------------------------
// fp32 -> bf16 hi/lo splits
// ---------------------------------------------------------------------------
__global__ void __launch_bounds__(256) split_kernel(
    const float* __restrict__ in, __nv_bfloat16* __restrict__ h,
    __nv_bfloat16* __restrict__ l, int n4)
{
    int i = blockIdx.x * 256 + threadIdx.x;
    if (i >= n4) return;
    float4 v = ((const float4*)in)[i];
    __nv_bfloat16 h0 = __float2bfloat16(v.x), h1 = __float2bfloat16(v.y);
    __nv_bfloat16 h2 = __float2bfloat16(v.z), h3 = __float2bfloat16(v.w);
    ((__nv_bfloat162*)h)[2*i]   = __nv_bfloat162(h0, h1);
    ((__nv_bfloat162*)h)[2*i+1] = __nv_bfloat162(h2, h3);
    ((__nv_bfloat162*)l)[2*i]   = __nv_bfloat162(
        __float2bfloat16(v.x - __bfloat162float(h0)),
        __float2bfloat16(v.y - __bfloat162float(h1)));
    ((__nv_bfloat162*)l)[2*i+1] = __nv_bfloat162(
        __float2bfloat16(v.z - __bfloat162float(h2)),
        __float2bfloat16(v.w - __bfloat162float(h3)));
}

__global__ void __launch_bounds__(256) wsplit_kernel(
    const float* __restrict__ w0, const float* __restrict__ w1,
    const float* __restrict__ w2, const float* __restrict__ w3,
    __nv_bfloat16* __restrict__ h, __nv_bfloat16* __restrict__ l)
{
    const int mat = blockIdx.y;
    const float* in = (mat == 0) ? w0 : (mat == 1) ? w1 : (mat == 2) ? w2 : w3;
    int i = blockIdx.x * 256 + threadIdx.x;
    const int n4 = DMODEL * DMODEL / 4;
    if (i >= n4) return;
    float4 v = ((const float4*)in)[i];
    size_t o = (size_t)mat * (DMODEL * DMODEL / 2) + 2 * i;
    __nv_bfloat16 h0 = __float2bfloat16(v.x), h1 = __float2bfloat16(v.y);
    __nv_bfloat16 h2 = __float2bfloat16(v.z), h3 = __float2bfloat16(v.w);
    ((__nv_bfloat162*)h)[o]   = __nv_bfloat162(h0, h1);
    ((__nv_bfloat162*)h)[o+1] = __nv_bfloat162(h2, h3);
    ((__nv_bfloat162*)l)[o]   = __nv_bfloat162(
        __float2bfloat16(v.x - __bfloat162float(h0)),
        __float2bfloat16(v.y - __bfloat162float(h1)));
    ((__nv_bfloat162*)l)[o+1] = __nv_bfloat162(
        __float2bfloat16(v.z - __bfloat162float(h2)),
        __float2bfloat16(v.w - __bfloat162float(h3)));
}

// ---------------------------------------------------------------------------
// GEMM core: BM=128 BN=64 BK=32, 256 thr, 3-stage cp.async, ONE sync per step.
// ---------------------------------------------------------------------------
#define ST_BYTES 30720

struct GemmCore {
    const char* gb[6];
    uint32_t so[6];
    uint32_t a_fb, b_fb;
    float acc[2][4][4];
};

__device__ __forceinline__ void gemm_setup(
    GemmCore& g, int tid, int lane, int wm, int wn, int m0, int n0,
    const __nv_bfloat16* Ah, const __nv_bfloat16* Al,
    const __nv_bfloat16* Wh, const __nv_bfloat16* Wl)
{
    constexpr int K = DMODEL;
    #pragma unroll
    for (int j = 0; j < 6; j++) {
        int c = tid + j * 256;
        if (c < 1024) {
            int split = c >> 9, cc = c & 511, row = cc >> 2, col = cc & 3;
            g.gb[j] = (const char*)((split ? Al : Ah) + (size_t)(m0 + row) * K) + col * 16;
            g.so[j] = split * 10240 + row * 80 + col * 16;
        } else {
            int cc = c - 1024, split = cc >> 8;
            cc &= 255; int row = cc >> 2, col = cc & 3;
            g.gb[j] = (const char*)((split ? Wl : Wh) + (size_t)(n0 + row) * K) + col * 16;
            g.so[j] = 20480 + split * 5120 + row * 80 + col * 16;
        }
    }
    g.a_fb = (wm * 32 + (lane & 15)) * 80 + (lane >> 4) * 16;
    g.b_fb = 20480 + (wn * 32 + (lane & 15)) * 80 + (lane >> 4) * 16;
    #pragma unroll
    for (int mt = 0; mt < 2; mt++)
        #pragma unroll
        for (int nt = 0; nt < 4; nt++)
            #pragma unroll
            for (int i = 0; i < 4; i++) g.acc[mt][nt][i] = 0.f;
}

__device__ __forceinline__ void gemm_main(GemmCore& g, uint32_t sb) {
    constexpr int NKT = DMODEL / 32;   // 10
    #pragma unroll
    for (int p = 0; p < 2; p++) {
        #pragma unroll
        for (int j = 0; j < 6; j++)
            CP16(sb + p * ST_BYTES + g.so[j], g.gb[j] + p * 64);
        CP_COMMIT();
    }

    for (int kt = 0; kt < NKT; kt++) {
        CP_WAIT(1);
        __syncthreads();
        {
            int pre = kt + 2;
            if (pre < NKT) {
                uint32_t stb = sb + (pre % 3) * ST_BYTES;
                #pragma unroll
                for (int j = 0; j < 6; j++)
                    CP16(stb + g.so[j], g.gb[j] + pre * 64);
            }
            CP_COMMIT();
        }

        const uint32_t ah_b = sb + (kt % 3) * ST_BYTES + g.a_fb;
        const uint32_t bh_b = sb + (kt % 3) * ST_BYTES + g.b_fb;
        #pragma unroll
        for (int kk = 0; kk < 2; kk++) {
            uint32_t ah[2][4], al[2][4], bh[2][4], bl[2][4];
            ldm4(ah[0], ah_b + kk * 32);
            ldm4(ah[1], ah_b + 1280 + kk * 32);
            ldm4(al[0], ah_b + 10240 + kk * 32);
            ldm4(al[1], ah_b + 11520 + kk * 32);
            ldm4(bh[0], bh_b + kk * 32);
            ldm4(bh[1], bh_b + 1280 + kk * 32);
            ldm4(bl[0], bh_b + 5120 + kk * 32);
            ldm4(bl[1], bh_b + 6400 + kk * 32);
            #pragma unroll
            for (int mt = 0; mt < 2; mt++)
                #pragma unroll
                for (int gg = 0; gg < 2; gg++)
                    #pragma unroll
                    for (int s = 0; s < 2; s++) {
                        float* c = g.acc[mt][gg * 2 + s];
                        mma_bf16(c, ah[mt][0], ah[mt][1], ah[mt][2], ah[mt][3],
                                 bh[gg][s], bh[gg][s + 2]);
                        mma_bf16(c, ah[mt][0], ah[mt][1], ah[mt][2], ah[mt][3],
                                 bl[gg][s], bl[gg][s + 2]);
                        mma_bf16(c, al[mt][0], al[mt][1], al[mt][2], al[mt][3],
                                 bh[gg][s], bh[gg][s + 2]);
                    }
        }
    }
}

// ---------------------------------------------------------------------------
// Fused QKV projection: blockIdx.z = 0:Q(bf16), 1:K(bf16 frag), 2:V(hi+colsum)
// ---------------------------------------------------------------------------
__global__ void __launch_bounds__(256) gemm_qkv(
    const __nv_bfloat16* __restrict__ Ah, const __nv_bfloat16* __restrict__ Al,
    const __nv_bfloat16* __restrict__ Whb, const __nv_bfloat16* __restrict__ Wlb,
    __nv_bfloat16* __restrict__ Qt, uint32_t* __restrict__ Kf,
    __nv_bfloat16* __restrict__ Vh, float* __restrict__ Part)
{
    extern __shared__ __align__(16) char sm[];
    const int tid = threadIdx.x, lane = tid & 31, w = tid >> 5;
    const int wm = w & 3, wn = w >> 2;
    const int m0 = blockIdx.y * 128, n0 = blockIdx.x * 64;
    const int mode = blockIdx.z;
    const uint32_t sb = smem_u32(sm);

    GemmCore g;
    gemm_setup(g, tid, lane, wm, wn, m0, n0,
               Ah, Al, Whb + (size_t)mode * DMODEL * DMODEL,
               Wlb + (size_t)mode * DMODEL * DMODEL);
    gemm_main(g, sb);

    const int r = lane >> 2, c2 = (lane & 3) * 2;
    #pragma unroll
    for (int mt = 0; mt < 2; mt++) {
        #pragma unroll
        for (int i = 0; i < 2; i++) {
            int m = m0 + wm * 32 + mt * 16 + r + i * 8;
            int b = m >> 12, s = m & (SEQ - 1);
            #pragma unroll
            for (int nt = 0; nt < 4; nt++) {
                float v0 = g.acc[mt][nt][i * 2], v1 = g.acc[mt][nt][i * 2 + 1];
                int n = n0 + wn * 32 + nt * 8 + c2;    // even
                int hd = n / DH, d = n - hd * DH;
                int bh = b * HEADS + hd;
                if (mode == 0) {
                    *(uint32_t*)&Qt[((size_t)bh * SEQ + s) * 48 + d] =
                        bf16x2(v1 * QSCALE, v0 * QSCALE);
                } else if (mode == 1) {
                    int tile = s >> 6, nn = s & 63;
                    int t = d >> 4, rem = d & 15;
                    int reg = rem >> 3, c = (rem >> 1) & 3;
                    size_t base = (size_t)(bh * NTILE + tile) * 1536;
                    if (t < 2)
                        Kf[base + ((nn * 4 + c) << 2) + t * 2 + reg] = bf16x2(v1, v0);
                    else
                        Kf[base + 1024 + ((nn * 4 + c) << 1) + reg] = bf16x2(v1, v0);
                } else {
                    size_t o = ((size_t)bh * DH + d) * SEQ + s;
                    Vh[o]       = __float2bfloat16(v0);
                    Vh[o + SEQ] = __float2bfloat16(v1);
                }
            }
        }
    }

    if (mode == 2) {
        __syncthreads();
        float* red = (float*)sm;         // [4][64]
        #pragma unroll
        for (int nt = 0; nt < 4; nt++) {
            float s0 = g.acc[0][nt][0] + g.acc[0][nt][2] + g.acc[1][nt][0] + g.acc[1][nt][2];
            float s1 = g.acc[0][nt][1] + g.acc[0][nt][3] + g.acc[1][nt][1] + g.acc[1][nt][3];
            #pragma unroll
            for (int msk = 4; msk <= 16; msk <<= 1) {
                s0 += __shfl_xor_sync(0xFFFFFFFFu, s0, msk);
                s1 += __shfl_xor_sync(0xFFFFFFFFu, s1, msk);
            }
            if (r == 0) {
                int col = wn * 32 + nt * 8 + c2;
                red[wm * 64 + col]     = s0;
                red[wm * 64 + col + 1] = s1;
            }
        }
        __syncthreads();
        if (tid < 64) {
            Part[(size_t)blockIdx.y * DMODEL + blockIdx.x * 64 + tid] =
                red[tid] + red[64 + tid] + red[128 + tid] + red[192 + tid];
        }
    }
}

// ---------------------------------------------------------------------------
// Out projection (fp32 + bias)
// ---------------------------------------------------------------------------
__global__ void __launch_bounds__(256) gemm_out(
    const __nv_bfloat16* __restrict__ Ah, const __nv_bfloat16* __restrict__ Al,
    const __nv_bfloat16* __restrict__ Wh, const __nv_bfloat16* __restrict__ Wl,
    const float* __restrict__ bias, float* __restrict__ Cf)
{
    extern __shared__ __align__(16) char sm[];
    const int tid = threadIdx.x, lane = tid & 31, w = tid >> 5;
    const int wm = w & 3, wn = w >> 2;
    const int m0 = blockIdx.y * 128, n0 = blockIdx.x * 64;
    const uint32_t sb = smem_u32(sm);

    GemmCore g;
    gemm_setup(g, tid, lane, wm, wn, m0, n0, Ah, Al, Wh, Wl);
    gemm_main(g, sb);

    const int r = lane >> 2, c2 = (lane & 3) * 2;
    #pragma unroll
    for (int mt = 0; mt < 2; mt++) {
        #pragma unroll
        for (int i = 0; i < 2; i++) {
            int m = m0 + wm * 32 + mt * 16 + r + i * 8;
            #pragma unroll
            for (int nt = 0; nt < 4; nt++) {
                int n = n0 + wn * 32 + nt * 8 + c2;
                float2 u = make_float2(g.acc[mt][nt][i*2] + bias[n],
                                       g.acc[mt][nt][i*2+1] + bias[n+1]);
                *(float2*)&Cf[(size_t)m * DMODEL + n] = u;
            }
        }
    }
}

// ---------------------------------------------------------------------------
// Flash attention: 4 warps x 32 q-rows (2 m-tiles/warp) — halves the
// cross-warp K/V smem replication. K/V fragments loaded once, reused by both
// m-tiles. Arithmetic identical to round 11/12 (bit-identical output).
// ---------------------------------------------------------------------------
#define KT_BYTES 6144
#define VROW     144
#define VT_BYTES (DH * VROW)                    // 5760
#define STAGE_BYTES (KT_BYTES + VT_BYTES)       // 11904
#define SM_ATTN (4 * STAGE_BYTES)               // 47616

__global__ void __launch_bounds__(128, 2) attn_kernel(
    const __nv_bfloat16* __restrict__ Qg, const char* __restrict__ Kf,
    const char* __restrict__ Vh, const float* __restrict__ Part,
    __nv_bfloat16* __restrict__ aoh, __nv_bfloat16* __restrict__ aol)
{
    extern __shared__ __align__(16) char smem[];
    __shared__ float cs_s[DH];
    const uint32_t sb = smem_u32(smem);
    const int tid = threadIdx.x, w = tid >> 5, lane = tid & 31;
    const int r4 = lane >> 2, c4 = lane & 3;
    const int bh = blockIdx.y, bB = bh >> 3, hh = bh & 7;
    const int q0 = blockIdx.x * 128;

    // cp.async chunks: K 384 + V 320 = 704 over 128 threads; 6 each (6th partial)
    const char* src[6]; uint32_t doff[6]; int adv[6];
    const bool ok5 = tid < 64;
    #pragma unroll
    for (int j = 0; j < 6; j++) {
        int cid = tid + j * 128;
        if (cid < 384) {
            src[j]  = Kf + (size_t)bh * (NTILE * KT_BYTES) + cid * 16;
            adv[j]  = KT_BYTES;
            doff[j] = cid * 16;
        } else if (cid < 704) {
            int v = cid - 384;
            int d = v >> 3, col = (v & 7) * 16;
            src[j]  = Vh + (((size_t)bh * DH + d) * SEQ) * 2 + col;
            adv[j]  = 128;
            doff[j] = KT_BYTES + d * VROW + col;
        } else {
            src[j] = nullptr; adv[j] = 0; doff[j] = 0;
        }
    }

    // prologue: prefetch 3 tiles
    #pragma unroll
    for (int p = 0; p < 3; p++) {
        #pragma unroll
        for (int j = 0; j < 5; j++)
            CP16(sb + p * STAGE_BYTES + doff[j], src[j] + (size_t)p * adv[j]);
        if (ok5) CP16(sb + p * STAGE_BYTES + doff[5], src[5] + (size_t)p * adv[5]);
        CP_COMMIT();
    }

    // exact V colsums for this (bh)
    if (tid < DH) {
        const float* pp = Part + (size_t)(bB * 32) * DMODEL + hh * DH + tid;
        float s = 0.f;
        #pragma unroll
        for (int j = 0; j < 32; j++) s += pp[(size_t)j * DMODEL];
        cs_s[tid] = s;
    }

    // Q A-fragments: 2 m-tiles per warp (rows 32w+16mt+r4, +8)
    const __nv_bfloat16* Qb = Qg + ((size_t)bh * SEQ + q0) * 48;
    uint32_t qa[2][3][4];
    #pragma unroll
    for (int mt = 0; mt < 2; mt++) {
        const int R = 32 * w + 16 * mt + r4;
        #pragma unroll
        for (int t = 0; t < 3; t++) {
            int k0 = 16 * t + 2 * c4;
            qa[mt][t][0] = *(const uint32_t*)(Qb + (size_t)R * 48 + k0);
            qa[mt][t][1] = *(const uint32_t*)(Qb + (size_t)(R + 8) * 48 + k0);
            qa[mt][t][2] = *(const uint32_t*)(Qb + (size_t)R * 48 + k0 + 8);
            qa[mt][t][3] = *(const uint32_t*)(Qb + (size_t)(R + 8) * 48 + k0 + 8);
        }
    }

    const uint32_t vl01 = ((lane & 7) + ((lane >> 4) << 3)) * VROW + ((lane >> 3) & 1) * 16;
    const uint32_t vl4  = (lane & 7) * VROW + ((lane >> 3) & 1) * 16;

    float o[2][5][4];
    #pragma unroll
    for (int mt = 0; mt < 2; mt++)
        #pragma unroll
        for (int b = 0; b < 5; b++) {
            o[mt][b][0]=0.f; o[mt][b][1]=0.f; o[mt][b][2]=0.f; o[mt][b][3]=0.f;
        }
    float lacc[2][4];
    #pragma unroll
    for (int mt = 0; mt < 2; mt++)
        #pragma unroll
        for (int j = 0; j < 4; j++) lacc[mt][j] = 0.f;

    for (int i = 0; i < NTILE; i++) {
        CP_WAIT(2);
        __syncthreads();

        {
            int pre = i + 3;
            if (pre < NTILE) {
                uint32_t stb = sb + (pre & 3) * STAGE_BYTES;
                #pragma unroll
                for (int j = 0; j < 5; j++)
                    CP16(stb + doff[j], src[j] + (size_t)pre * adv[j]);
                if (ok5) CP16(stb + doff[5], src[5] + (size_t)pre * adv[5]);
            }
            CP_COMMIT();
        }

        const int cur = i & 3;
        const uint4* kf4  = (const uint4*)(smem + cur * STAGE_BYTES);
        const uint2* kf2t = (const uint2*)(smem + cur * STAGE_BYTES + 4096);

        // MMA1: K frags loaded once, used by both m-tiles
        float s[2][8][4];
        #pragma unroll
        for (int mt = 0; mt < 2; mt++)
            #pragma unroll
            for (int b = 0; b < 8; b++) {
                s[mt][b][0]=0.f; s[mt][b][1]=0.f; s[mt][b][2]=0.f; s[mt][b][3]=0.f;
            }
        #pragma unroll
        for (int gq = 0; gq < 2; gq++) {
            uint4 kkA[4];
            #pragma unroll
            for (int b = 0; b < 4; b++)
                kkA[b] = kf4[((8 * (4 * gq + b) + r4) * 4 + c4)];
            #pragma unroll
            for (int b = 0; b < 4; b++)
                #pragma unroll
                for (int mt = 0; mt < 2; mt++)
                    mma_bf16(s[mt][4*gq+b], qa[mt][0][0], qa[mt][0][1],
                             qa[mt][0][2], qa[mt][0][3], kkA[b].x, kkA[b].y);
            #pragma unroll
            for (int b = 0; b < 4; b++)
                #pragma unroll
                for (int mt = 0; mt < 2; mt++)
                    mma_bf16(s[mt][4*gq+b], qa[mt][1][0], qa[mt][1][1],
                             qa[mt][1][2], qa[mt][1][3], kkA[b].z, kkA[b].w);
        }
        {
            uint2 kkB[8];
            #pragma unroll
            for (int b = 0; b < 8; b++)
                kkB[b] = kf2t[(8 * b + r4) * 4 + c4];
            #pragma unroll
            for (int b = 0; b < 8; b++)
                #pragma unroll
                for (int mt = 0; mt < 2; mt++)
                    mma_bf16(s[mt][b], qa[mt][2][0], qa[mt][2][1],
                             qa[mt][2][2], qa[mt][2][3], kkB[b].x, kkB[b].y);
        }

        // softmax per m-tile
        uint32_t pb[2][8][2];
        #pragma unroll
        for (int mt = 0; mt < 2; mt++)
            #pragma unroll
            for (int b = 0; b < 8; b++) {
                float p0 = ex2f(s[mt][b][0]), p1 = ex2f(s[mt][b][1]);
                float p2 = ex2f(s[mt][b][2]), p3 = ex2f(s[mt][b][3]);
                lacc[mt][0] += p0; lacc[mt][1] += p1;
                lacc[mt][2] += p2; lacc[mt][3] += p3;
                pb[mt][b][0] = bf16x2(p1 - 1.f, p0 - 1.f);
                pb[mt][b][1] = bf16x2(p3 - 1.f, p2 - 1.f);
            }

        // MMA2: V frags loaded once per t, used by both m-tiles
        const uint32_t vbase = sb + cur * STAGE_BYTES + KT_BYTES;
        #pragma unroll
        for (int t = 0; t < 4; t++) {
            uint32_t f[10];
            uint32_t hb0 = vbase + 32 * t;
            ldm4(f,     hb0 + vl01);
            ldm4(f + 4, hb0 + 16 * VROW + vl01);
            ldm2(f + 8, hb0 + 32 * VROW + vl4);
            #pragma unroll
            for (int mt = 0; mt < 2; mt++) {
                uint32_t a0 = pb[mt][2*t][0],   a1 = pb[mt][2*t][1];
                uint32_t a2 = pb[mt][2*t+1][0], a3 = pb[mt][2*t+1][1];
                #pragma unroll
                for (int b = 0; b < 5; b++)
                    mma_bf16(o[mt][b], a0, a1, a2, a3, f[2*b], f[2*b+1]);
            }
        }
    }

    // epilogue per m-tile
    #pragma unroll
    for (int mt = 0; mt < 2; mt++) {
        float l0 = lacc[mt][0] + lacc[mt][1], l1 = lacc[mt][2] + lacc[mt][3];
        l0 += __shfl_xor_sync(0xFFFFFFFFu, l0, 1);
        l0 += __shfl_xor_sync(0xFFFFFFFFu, l0, 2);
        l1 += __shfl_xor_sync(0xFFFFFFFFu, l1, 1);
        l1 += __shfl_xor_sync(0xFFFFFFFFu, l1, 2);
        const float inv0 = 1.f / l0, inv1 = 1.f / l1;

        const size_t base0 = ((size_t)bB * SEQ + q0 + 32 * w + 16 * mt + r4) * DMODEL
                             + hh * DH;
        const size_t base1 = base0 + (size_t)8 * DMODEL;
        #pragma unroll
        for (int b = 0; b < 5; b++) {
            int d0 = 8 * b + 2 * c4;
            float cs0 = cs_s[d0], cs1 = cs_s[d0 + 1];
            float u0 = (o[mt][b][0] + cs0) * inv0;
            float u1 = (o[mt][b][1] + cs1) * inv0;
            __nv_bfloat16 h0 = __float2bfloat16(u0), h1 = __float2bfloat16(u1);
            *(__nv_bfloat162*)&aoh[base0 + d0] = __nv_bfloat162(h0, h1);
            *(__nv_bfloat162*)&aol[base0 + d0] = __nv_bfloat162(
                __float2bfloat16(u0 - __bfloat162float(h0)),
                __float2bfloat16(u1 - __bfloat162float(h1)));
            float w0 = (o[mt][b][2] + cs0) * inv1;
            float w1 = (o[mt][b][3] + cs1) * inv1;
            __nv_bfloat16 g0 = __float2bfloat16(w0), g1 = __float2bfloat16(w1);
            *(__nv_bfloat162*)&aoh[base1 + d0] = __nv_bfloat162(g0, g1);
            *(__nv_bfloat162*)&aol[base1 + d0] = __nv_bfloat162(
                __float2bfloat16(w0 - __bfloat162float(g0)),
                __float2bfloat16(w1 - __bfloat162float(g1)));
        }
    }
}

// ---------------------------------------------------------------------------
extern "C" void kernel_launch(void* const* d_in, const int* in_sizes, int n_in,
                              void* d_out, int out_size)
{
    const float* x    = (const float*)d_in[0];
    const float* Wq   = (const float*)d_in[1];
    const float* Wk   = (const float*)d_in[2];
    const float* Wv   = (const float*)d_in[3];
    const float* Wout = (const float*)d_in[4];
    const float* bout = (const float*)d_in[5];
    float* out = (float*)d_out;

    __nv_bfloat16 *xh, *xl, *whp, *wlp, *vh, *aoh, *aol, *qt;
    uint32_t* kf;
    float *part;
    cudaGetSymbolAddress((void**)&xh,   g_xh);
    cudaGetSymbolAddress((void**)&xl,   g_xl);
    cudaGetSymbolAddress((void**)&whp,  g_wh);
    cudaGetSymbolAddress((void**)&wlp,  g_wl);
    cudaGetSymbolAddress((void**)&qt,   g_qt);
    cudaGetSymbolAddress((void**)&kf,   g_kf);
    cudaGetSymbolAddress((void**)&vh,   g_vh);
    cudaGetSymbolAddress((void**)&part, g_part);
    cudaGetSymbolAddress((void**)&aoh,  g_aoh);
    cudaGetSymbolAddress((void**)&aol,  g_aol);

    const int WSZ = DMODEL * DMODEL;
    cudaFuncSetAttribute(gemm_qkv, cudaFuncAttributeMaxDynamicSharedMemorySize, 3*ST_BYTES);
    cudaFuncSetAttribute(gemm_out, cudaFuncAttributeMaxDynamicSharedMemorySize, 3*ST_BYTES);
    cudaFuncSetAttribute(attn_kernel, cudaFuncAttributeMaxDynamicSharedMemorySize, SM_ATTN);

    split_kernel<<<(MTOT*DMODEL/4 + 255)/256, 256>>>(x, xh, xl, MTOT*DMODEL/4);
    dim3 gws((WSZ/4 + 255)/256, 4);
    wsplit_kernel<<<gws, 256>>>(Wq, Wk, Wv, Wout, whp, wlp);

    dim3 gqkv(DMODEL / 64, MTOT / 128, 3);   // (5, 64, 3)
    gemm_qkv<<<gqkv, 256, 3*ST_BYTES>>>(xh, xl, whp, wlp, qt, kf, vh, part);

    dim3 gattn(SEQ / 128, NBH);              // (32, 16), 128 threads now
    attn_kernel<<<gattn, 128, SM_ATTN>>>(qt, (const char*)kf, (const char*)vh,
                                         part, aoh, aol);

    dim3 gout(DMODEL / 64, MTOT / 128);      // (5, 64)
    gemm_out<<<gout, 256, 3*ST_BYTES>>>(aoh, aol, whp + 3*WSZ, wlp + 3*WSZ,
                                        bout, out);
}

// round 14
// speedup vs baseline: 1.0709x; 1.0197x over previous
#include <cuda_runtime.h>
#include <cuda_bf16.h>
#include <cstdint>

#define BATCH  2
#define SEQ    4096
#define DMODEL 320
#define HEADS  8
#define DH     40
#define MTOT   (BATCH*SEQ)
#define NBH    (BATCH*HEADS)
#define SCALE  0.15811388300841897f
#define LOG2E  1.4426950408889634f
#define QSCALE (SCALE*LOG2E)
#define NTILE  (SEQ/64)

typedef unsigned long long ull;

// ---- scratch (static device arrays; zero-initialized => padding stays 0) ----
__device__ __nv_bfloat16 g_xh[(size_t)MTOT*DMODEL];
__device__ __nv_bfloat16 g_xl[(size_t)MTOT*DMODEL];
__device__ __nv_bfloat16 g_wh[4][DMODEL*DMODEL];
__device__ __nv_bfloat16 g_wl[4][DMODEL*DMODEL];
__device__ __nv_bfloat16 g_qt[(size_t)NBH*SEQ*48];      // Q*QSCALE bf16, dims 40..47 = 0
__device__ uint32_t      g_kf[(size_t)NBH*NTILE*1280];  // K frag: t01 uint4 | t2 uint1
__device__ __nv_bfloat16 g_vh[(size_t)NBH*DH*SEQ];      // V hi bf16 [bh][d][s]
__device__ float         g_part[64][DMODEL];            // per-m-block exact V colsums
__device__ __nv_bfloat16 g_aoh[(size_t)MTOT*DMODEL];
__device__ __nv_bfloat16 g_aol[(size_t)MTOT*DMODEL];

// ---- helpers ----
__device__ __forceinline__ float ex2f(float x) {
    float y; asm("ex2.approx.ftz.f32 %0, %1;" : "=f"(y) : "f"(x)); return y;
}
__device__ __forceinline__ uint32_t bf16x2(float hi, float lo) {
    uint32_t r; asm("cvt.rn.bf16x2.f32 %0, %1, %2;" : "=r"(r) : "f"(hi), "f"(lo)); return r;
}
__device__ __forceinline__ uint32_t smem_u32(const void* p) {
    uint32_t a;
    asm("{ .reg .u64 t; cvta.to.shared.u64 t, %1; cvt.u32.u64 %0, t; }" : "=r"(a) : "l"(p));
    return a;
}
__device__ __forceinline__ void mma_bf16(float* c, uint32_t a0, uint32_t a1,
                                         uint32_t a2, uint32_t a3, uint32_t b0, uint32_t b1) {
    asm volatile("mma.sync.aligned.m16n8k16.row.col.f32.bf16.bf16.f32 "
        "{%0,%1,%2,%3}, {%4,%5,%6,%7}, {%8,%9}, {%0,%1,%2,%3};"
        : "+f"(c[0]), "+f"(c[1]), "+f"(c[2]), "+f"(c[3])
        : "r"(a0), "r"(a1), "r"(a2), "r"(a3), "r"(b0), "r"(b1));
}
__device__ __forceinline__ void mma_bf16_k8(float* c, uint32_t a0, uint32_t a1,
                                            uint32_t b0) {
    asm volatile("mma.sync.aligned.m16n8k8.row.col.f32.bf16.bf16.f32 "
        "{%0,%1,%2,%3}, {%4,%5}, {%6}, {%0,%1,%2,%3};"
        : "+f"(c[0]), "+f"(c[1]), "+f"(c[2]), "+f"(c[3])
        : "r"(a0), "r"(a1), "r"(b0));
}
__device__ __forceinline__ void ldm4(uint32_t* r, uint32_t addr) {
    asm volatile("ldmatrix.sync.aligned.m8n8.x4.shared.b16 {%0,%1,%2,%3}, [%4];"
        : "=r"(r[0]), "=r"(r[1]), "=r"(r[2]), "=r"(r[3]) : "r"(addr));
}
__device__ __forceinline__ void ldm2(uint32_t* r, uint32_t addr) {
    asm volatile("ldmatrix.sync.aligned.m8n8.x2.shared.b16 {%0,%1}, [%2];"
        : "=r"(r[0]), "=r"(r[1]) : "r"(addr));
}
#define CP16(s, g) asm volatile("cp.async.ca.shared.global [%0], [%1], 16;" :: "r"(s), "l"(g))
#define CP_COMMIT() asm volatile("cp.async.commit_group;" ::: "memory")
#define CP_WAIT(n)  asm volatile("cp.async.wait_group %0;" :: "n"(n) : "memory")

// ---------------------------------------------------------------------------
// fp32 -> bf16 hi/lo splits
// ---------------------------------------------------------------------------
__global__ void __launch_bounds__(256) split_kernel(
    const float* __restrict__ in, __nv_bfloat16* __restrict__ h,
    __nv_bfloat16* __restrict__ l, int n4)
{
    int i = blockIdx.x * 256 + threadIdx.x;
    if (i >= n4) return;
    float4 v = ((const float4*)in)[i];
    __nv_bfloat16 h0 = __float2bfloat16(v.x), h1 = __float2bfloat16(v.y);
    __nv_bfloat16 h2 = __float2bfloat16(v.z), h3 = __float2bfloat16(v.w);
    ((__nv_bfloat162*)h)[2*i]   = __nv_bfloat162(h0, h1);
    ((__nv_bfloat162*)h)[2*i+1] = __nv_bfloat162(h2, h3);
    ((__nv_bfloat162*)l)[2*i]   = __nv_bfloat162(
        __float2bfloat16(v.x - __bfloat162float(h0)),
        __float2bfloat16(v.y - __bfloat162float(h1)));
    ((__nv_bfloat162*)l)[2*i+1] = __nv_bfloat162(
        __float2bfloat16(v.z - __bfloat162float(h2)),
        __float2bfloat16(v.w - __bfloat162float(h3)));
}

__global__ void __launch_bounds__(256) wsplit_kernel(
    const float* __restrict__ w0, const float* __restrict__ w1,
    const float* __restrict__ w2, const float* __restrict__ w3,
    __nv_bfloat16* __restrict__ h, __nv_bfloat16* __restrict__ l)
{
    const int mat = blockIdx.y;
    const float* in = (mat == 0) ? w0 : (mat == 1) ? w1 : (mat == 2) ? w2 : w3;
    int i = blockIdx.x * 256 + threadIdx.x;
    const int n4 = DMODEL * DMODEL / 4;
    if (i >= n4) return;
    float4 v = ((const float4*)in)[i];
    size_t o = (size_t)mat * (DMODEL * DMODEL / 2) + 2 * i;
    __nv_bfloat16 h0 = __float2bfloat16(v.x), h1 = __float2bfloat16(v.y);
    __nv_bfloat16 h2 = __float2bfloat16(v.z), h3 = __float2bfloat16(v.w);
    ((__nv_bfloat162*)h)[o]   = __nv_bfloat162(h0, h1);
    ((__nv_bfloat162*)h)[o+1] = __nv_bfloat162(h2, h3);
    ((__nv_bfloat162*)l)[o]   = __nv_bfloat162(
        __float2bfloat16(v.x - __bfloat162float(h0)),
        __float2bfloat16(v.y - __bfloat162float(h1)));
    ((__nv_bfloat162*)l)[o+1] = __nv_bfloat162(
        __float2bfloat16(v.z - __bfloat162float(h2)),
        __float2bfloat16(v.w - __bfloat162float(h3)));
}

// ---------------------------------------------------------------------------
// GEMM core: BM=128 BN=64 BK=32, 256 thr, 3-stage cp.async, ONE sync per step.
// ---------------------------------------------------------------------------
#define ST_BYTES 30720

struct GemmCore {
    const char* gb[6];
    uint32_t so[6];
    uint32_t a_fb, b_fb;
    float acc[2][4][4];
};

__device__ __forceinline__ void gemm_setup(
    GemmCore& g, int tid, int lane, int wm, int wn, int m0, int n0,
    const __nv_bfloat16* Ah, const __nv_bfloat16* Al,
    const __nv_bfloat16* Wh, const __nv_bfloat16* Wl)
{
    constexpr int K = DMODEL;
    #pragma unroll
    for (int j = 0; j < 6; j++) {
        int c = tid + j * 256;
        if (c < 1024) {
            int split = c >> 9, cc = c & 511, row = cc >> 2, col = cc & 3;
            g.gb[j] = (const char*)((split ? Al : Ah) + (size_t)(m0 + row) * K) + col * 16;
            g.so[j] = split * 10240 + row * 80 + col * 16;
        } else {
            int cc = c - 1024, split = cc >> 8;
            cc &= 255; int row = cc >> 2, col = cc & 3;
            g.gb[j] = (const char*)((split ? Wl : Wh) + (size_t)(n0 + row) * K) + col * 16;
            g.so[j] = 20480 + split * 5120 + row * 80 + col * 16;
        }
    }
    g.a_fb = (wm * 32 + (lane & 15)) * 80 + (lane >> 4) * 16;
    g.b_fb = 20480 + (wn * 32 + (lane & 15)) * 80 + (lane >> 4) * 16;
    #pragma unroll
    for (int mt = 0; mt < 2; mt++)
        #pragma unroll
        for (int nt = 0; nt < 4; nt++)
            #pragma unroll
            for (int i = 0; i < 4; i++) g.acc[mt][nt][i] = 0.f;
}

__device__ __forceinline__ void gemm_main(GemmCore& g, uint32_t sb) {
    constexpr int NKT = DMODEL / 32;   // 10
    #pragma unroll
    for (int p = 0; p < 2; p++) {
        #pragma unroll
        for (int j = 0; j < 6; j++)
            CP16(sb + p * ST_BYTES + g.so[j], g.gb[j] + p * 64);
        CP_COMMIT();
    }

    for (int kt = 0; kt < NKT; kt++) {
        CP_WAIT(1);
        __syncthreads();
        {
            int pre = kt + 2;
            if (pre < NKT) {
                uint32_t stb = sb + (pre % 3) * ST_BYTES;
                #pragma unroll
                for (int j = 0; j < 6; j++)
                    CP16(stb + g.so[j], g.gb[j] + pre * 64);
            }
            CP_COMMIT();
        }

        const uint32_t ah_b = sb + (kt % 3) * ST_BYTES + g.a_fb;
        const uint32_t bh_b = sb + (kt % 3) * ST_BYTES + g.b_fb;
        #pragma unroll
        for (int kk = 0; kk < 2; kk++) {
            uint32_t ah[2][4], al[2][4], bh[2][4], bl[2][4];
            ldm4(ah[0], ah_b + kk * 32);
            ldm4(ah[1], ah_b + 1280 + kk * 32);
            ldm4(al[0], ah_b + 10240 + kk * 32);
            ldm4(al[1], ah_b + 11520 + kk * 32);
            ldm4(bh[0], bh_b + kk * 32);
            ldm4(bh[1], bh_b + 1280 + kk * 32);
            ldm4(bl[0], bh_b + 5120 + kk * 32);
            ldm4(bl[1], bh_b + 6400 + kk * 32);
            #pragma unroll
            for (int mt = 0; mt < 2; mt++)
                #pragma unroll
                for (int gg = 0; gg < 2; gg++)
                    #pragma unroll
                    for (int s = 0; s < 2; s++) {
                        float* c = g.acc[mt][gg * 2 + s];
                        mma_bf16(c, ah[mt][0], ah[mt][1], ah[mt][2], ah[mt][3],
                                 bh[gg][s], bh[gg][s + 2]);
                        mma_bf16(c, ah[mt][0], ah[mt][1], ah[mt][2], ah[mt][3],
                                 bl[gg][s], bl[gg][s + 2]);
                        mma_bf16(c, al[mt][0], al[mt][1], al[mt][2], al[mt][3],
                                 bh[gg][s], bh[gg][s + 2]);
                    }
        }
    }
}

// ---------------------------------------------------------------------------
// Fused QKV projection: blockIdx.z = 0:Q(bf16), 1:K(bf16 frag), 2:V(hi+colsum)
// ---------------------------------------------------------------------------
__global__ void __launch_bounds__(256) gemm_qkv(
    const __nv_bfloat16* __restrict__ Ah, const __nv_bfloat16* __restrict__ Al,
    const __nv_bfloat16* __restrict__ Whb, const __nv_bfloat16* __restrict__ Wlb,
    __nv_bfloat16* __restrict__ Qt, uint32_t* __restrict__ Kf,
    __nv_bfloat16* __restrict__ Vh, float* __restrict__ Part)
{
    extern __shared__ __align__(16) char sm[];
    const int tid = threadIdx.x, lane = tid & 31, w = tid >> 5;
    const int wm = w & 3, wn = w >> 2;
    const int m0 = blockIdx.y * 128, n0 = blockIdx.x * 64;
    const int mode = blockIdx.z;
    const uint32_t sb = smem_u32(sm);

    GemmCore g;
    gemm_setup(g, tid, lane, wm, wn, m0, n0,
               Ah, Al, Whb + (size_t)mode * DMODEL * DMODEL,
               Wlb + (size_t)mode * DMODEL * DMODEL);
    gemm_main(g, sb);

    const int r = lane >> 2, c2 = (lane & 3) * 2;
    #pragma unroll
    for (int mt = 0; mt < 2; mt++) {
        #pragma unroll
        for (int i = 0; i < 2; i++) {
            int m = m0 + wm * 32 + mt * 16 + r + i * 8;
            int b = m >> 12, s = m & (SEQ - 1);
            #pragma unroll
            for (int nt = 0; nt < 4; nt++) {
                float v0 = g.acc[mt][nt][i * 2], v1 = g.acc[mt][nt][i * 2 + 1];
                int n = n0 + wn * 32 + nt * 8 + c2;    // even
                int hd = n / DH, d = n - hd * DH;
                int bh = b * HEADS + hd;
                if (mode == 0) {
                    *(uint32_t*)&Qt[((size_t)bh * SEQ + s) * 48 + d] =
                        bf16x2(v1 * QSCALE, v0 * QSCALE);
                } else if (mode == 1) {
                    // K frag: t0/t1 as uint4 at (nn*4+c)*4 + t*2 + reg,
                    //         t2 (k8 B-frag) single uint32 at 1024 + nn*4+c
                    int tile = s >> 6, nn = s & 63;
                    int t = d >> 4, rem = d & 15;
                    int reg = rem >> 3, c = (rem >> 1) & 3;
                    size_t base = (size_t)(bh * NTILE + tile) * 1280;
                    if (t < 2)
                        Kf[base + ((nn * 4 + c) << 2) + t * 2 + reg] = bf16x2(v1, v0);
                    else
                        Kf[base + 1024 + nn * 4 + c] = bf16x2(v1, v0);
                } else {
                    size_t o = ((size_t)bh * DH + d) * SEQ + s;
                    Vh[o]       = __float2bfloat16(v0);
                    Vh[o + SEQ] = __float2bfloat16(v1);
                }
            }
        }
    }

    if (mode == 2) {
        __syncthreads();
        float* red = (float*)sm;         // [4][64]
        #pragma unroll
        for (int nt = 0; nt < 4; nt++) {
            float s0 = g.acc[0][nt][0] + g.acc[0][nt][2] + g.acc[1][nt][0] + g.acc[1][nt][2];
            float s1 = g.acc[0][nt][1] + g.acc[0][nt][3] + g.acc[1][nt][1] + g.acc[1][nt][3];
            #pragma unroll
            for (int msk = 4; msk <= 16; msk <<= 1) {
                s0 += __shfl_xor_sync(0xFFFFFFFFu, s0, msk);
                s1 += __shfl_xor_sync(0xFFFFFFFFu, s1, msk);
            }
            if (r == 0) {
                int col = wn * 32 + nt * 8 + c2;
                red[wm * 64 + col]     = s0;
                red[wm * 64 + col + 1] = s1;
            }
        }
        __syncthreads();
        if (tid < 64) {
            Part[(size_t)blockIdx.y * DMODEL + blockIdx.x * 64 + tid] =
                red[tid] + red[64 + tid] + red[128 + tid] + red[192 + tid];
        }
    }
}

// ---------------------------------------------------------------------------
// Out projection (fp32 + bias)
// ---------------------------------------------------------------------------
__global__ void __launch_bounds__(256) gemm_out(
    const __nv_bfloat16* __restrict__ Ah, const __nv_bfloat16* __restrict__ Al,
    const __nv_bfloat16* __restrict__ Wh, const __nv_bfloat16* __restrict__ Wl,
    const float* __restrict__ bias, float* __restrict__ Cf)
{
    extern __shared__ __align__(16) char sm[];
    const int tid = threadIdx.x, lane = tid & 31, w = tid >> 5;
    const int wm = w & 3, wn = w >> 2;
    const int m0 = blockIdx.y * 128, n0 = blockIdx.x * 64;
    const uint32_t sb = smem_u32(sm);

    GemmCore g;
    gemm_setup(g, tid, lane, wm, wn, m0, n0, Ah, Al, Wh, Wl);
    gemm_main(g, sb);

    const int r = lane >> 2, c2 = (lane & 3) * 2;
    #pragma unroll
    for (int mt = 0; mt < 2; mt++) {
        #pragma unroll
        for (int i = 0; i < 2; i++) {
            int m = m0 + wm * 32 + mt * 16 + r + i * 8;
            #pragma unroll
            for (int nt = 0; nt < 4; nt++) {
                int n = n0 + wn * 32 + nt * 8 + c2;
                float2 u = make_float2(g.acc[mt][nt][i*2] + bias[n],
                                       g.acc[mt][nt][i*2+1] + bias[n+1]);
                *(float2*)&Cf[(size_t)m * DMODEL + n] = u;
            }
        }
    }
}

// ---------------------------------------------------------------------------
// Flash attention: 4 warps x 32 q-rows, k8 tail MMA (no padded tensor work).
// ---------------------------------------------------------------------------
#define KT_BYTES 5120
#define VROW     144
#define VT_BYTES (DH * VROW)                    // 5760
#define STAGE_BYTES (KT_BYTES + VT_BYTES)       // 10880
#define SM_ATTN (4 * STAGE_BYTES)               // 43520

__global__ void __launch_bounds__(128, 2) attn_kernel(
    const __nv_bfloat16* __restrict__ Qg, const char* __restrict__ Kf,
    const char* __restrict__ Vh, const float* __restrict__ Part,
    __nv_bfloat16* __restrict__ aoh, __nv_bfloat16* __restrict__ aol)
{
    extern __shared__ __align__(16) char smem[];
    __shared__ float cs_s[DH];
    const uint32_t sb = smem_u32(smem);
    const int tid = threadIdx.x, w = tid >> 5, lane = tid & 31;
    const int r4 = lane >> 2, c4 = lane & 3;
    const int bh = blockIdx.y, bB = bh >> 3, hh = bh & 7;
    const int q0 = blockIdx.x * 128;

    // cp.async chunks: K 320 + V 320 = 640 over 128 threads = 5 each (exact)
    const char* src[5]; uint32_t doff[5]; int adv[5];
    #pragma unroll
    for (int j = 0; j < 5; j++) {
        int cid = tid + j * 128;
        if (cid < 320) {
            src[j]  = Kf + (size_t)bh * (NTILE * KT_BYTES) + cid * 16;
            adv[j]  = KT_BYTES;
            doff[j] = cid * 16;
        } else {
            int v = cid - 320;
            int d = v >> 3, col = (v & 7) * 16;
            src[j]  = Vh + (((size_t)bh * DH + d) * SEQ) * 2 + col;
            adv[j]  = 128;
            doff[j] = KT_BYTES + d * VROW + col;
        }
    }

    // prologue: prefetch 3 tiles
    #pragma unroll
    for (int p = 0; p < 3; p++) {
        #pragma unroll
        for (int j = 0; j < 5; j++)
            CP16(sb + p * STAGE_BYTES + doff[j], src[j] + (size_t)p * adv[j]);
        CP_COMMIT();
    }

    // exact V colsums for this (bh)
    if (tid < DH) {
        const float* pp = Part + (size_t)(bB * 32) * DMODEL + hh * DH + tid;
        float s = 0.f;
        #pragma unroll
        for (int j = 0; j < 32; j++) s += pp[(size_t)j * DMODEL];
        cs_s[tid] = s;
    }

    // Q A-fragments: 2 m-tiles per warp; t2 needs only 2 regs (k8 A-fragment)
    const __nv_bfloat16* Qb = Qg + ((size_t)bh * SEQ + q0) * 48;
    uint32_t qa[2][2][4], qa2[2][2];
    #pragma unroll
    for (int mt = 0; mt < 2; mt++) {
        const int R = 32 * w + 16 * mt + r4;
        #pragma unroll
        for (int t = 0; t < 2; t++) {
            int k0 = 16 * t + 2 * c4;
            qa[mt][t][0] = *(const uint32_t*)(Qb + (size_t)R * 48 + k0);
            qa[mt][t][1] = *(const uint32_t*)(Qb + (size_t)(R + 8) * 48 + k0);
            qa[mt][t][2] = *(const uint32_t*)(Qb + (size_t)R * 48 + k0 + 8);
            qa[mt][t][3] = *(const uint32_t*)(Qb + (size_t)(R + 8) * 48 + k0 + 8);
        }
        int k2 = 32 + 2 * c4;
        qa2[mt][0] = *(const uint32_t*)(Qb + (size_t)R * 48 + k2);
        qa2[mt][1] = *(const uint32_t*)(Qb + (size_t)(R + 8) * 48 + k2);
    }

    const uint32_t vl01 = ((lane & 7) + ((lane >> 4) << 3)) * VROW + ((lane >> 3) & 1) * 16;
    const uint32_t vl4  = (lane & 7) * VROW + ((lane >> 3) & 1) * 16;

    float o[2][5][4];
    #pragma unroll
    for (int mt = 0; mt < 2; mt++)
        #pragma unroll
        for (int b = 0; b < 5; b++) {
            o[mt][b][0]=0.f; o[mt][b][1]=0.f; o[mt][b][2]=0.f; o[mt][b][3]=0.f;
        }
    float lacc[2][4];
    #pragma unroll
    for (int mt = 0; mt < 2; mt++)
        #pragma unroll
        for (int j = 0; j < 4; j++) lacc[mt][j] = 0.f;

    for (int i = 0; i < NTILE; i++) {
        CP_WAIT(2);
        __syncthreads();

        {
            int pre = i + 3;
            if (pre < NTILE) {
                uint32_t stb = sb + (pre & 3) * STAGE_BYTES;
                #pragma unroll
                for (int j = 0; j < 5; j++)
                    CP16(stb + doff[j], src[j] + (size_t)pre * adv[j]);
            }
            CP_COMMIT();
        }

        const int cur = i & 3;
        const uint4* kf4     = (const uint4*)(smem + cur * STAGE_BYTES);
        const uint32_t* kf1t = (const uint32_t*)(smem + cur * STAGE_BYTES + 4096);

        // MMA1: K frags loaded once, used by both m-tiles; t2 via m16n8k8
        float s[2][8][4];
        #pragma unroll
        for (int mt = 0; mt < 2; mt++)
            #pragma unroll
            for (int b = 0; b < 8; b++) {
                s[mt][b][0]=0.f; s[mt][b][1]=0.f; s[mt][b][2]=0.f; s[mt][b][3]=0.f;
            }
        #pragma unroll
        for (int gq = 0; gq < 2; gq++) {
            uint4 kkA[4];
            #pragma unroll
            for (int b = 0; b < 4; b++)
                kkA[b] = kf4[((8 * (4 * gq + b) + r4) * 4 + c4)];
            #pragma unroll
            for (int b = 0; b < 4; b++)
                #pragma unroll
                for (int mt = 0; mt < 2; mt++)
                    mma_bf16(s[mt][4*gq+b], qa[mt][0][0], qa[mt][0][1],
                             qa[mt][0][2], qa[mt][0][3], kkA[b].x, kkA[b].y);
            #pragma unroll
            for (int b = 0; b < 4; b++)
                #pragma unroll
                for (int mt = 0; mt < 2; mt++)
                    mma_bf16(s[mt][4*gq+b], qa[mt][1][0], qa[mt][1][1],
                             qa[mt][1][2], qa[mt][1][3], kkA[b].z, kkA[b].w);
        }
        {
            uint32_t kkB[8];
            #pragma unroll
            for (int b = 0; b < 8; b++)
                kkB[b] = kf1t[(8 * b + r4) * 4 + c4];
            #pragma unroll
            for (int b = 0; b < 8; b++)
                #pragma unroll
                for (int mt = 0; mt < 2; mt++)
                    mma_bf16_k8(s[mt][b], qa2[mt][0], qa2[mt][1], kkB[b]);
        }

        // softmax per m-tile
        uint32_t pb[2][8][2];
        #pragma unroll
        for (int mt = 0; mt < 2; mt++)
            #pragma unroll
            for (int b = 0; b < 8; b++) {
                float p0 = ex2f(s[mt][b][0]), p1 = ex2f(s[mt][b][1]);
                float p2 = ex2f(s[mt][b][2]), p3 = ex2f(s[mt][b][3]);
                lacc[mt][0] += p0; lacc[mt][1] += p1;
                lacc[mt][2] += p2; lacc[mt][3] += p3;
                pb[mt][b][0] = bf16x2(p1 - 1.f, p0 - 1.f);
                pb[mt][b][1] = bf16x2(p3 - 1.f, p2 - 1.f);
            }

        // MMA2: V frags loaded once per t, used by both m-tiles
        const uint32_t vbase = sb + cur * STAGE_BYTES + KT_BYTES;
        #pragma unroll
        for (int t = 0; t < 4; t++) {
            uint32_t f[10];
            uint32_t hb0 = vbase + 32 * t;
            ldm4(f,     hb0 + vl01);
            ldm4(f + 4, hb0 + 16 * VROW + vl01);
            ldm2(f + 8, hb0 + 32 * VROW + vl4);
            #pragma unroll
            for (int mt = 0; mt < 2; mt++) {
                uint32_t a0 = pb[mt][2*t][0],   a1 = pb[mt][2*t][1];
                uint32_t a2 = pb[mt][2*t+1][0], a3 = pb[mt][2*t+1][1];
                #pragma unroll
                for (int b = 0; b < 5; b++)
                    mma_bf16(o[mt][b], a0, a1, a2, a3, f[2*b], f[2*b+1]);
            }
        }
    }

    // epilogue per m-tile
    #pragma unroll
    for (int mt = 0; mt < 2; mt++) {
        float l0 = lacc[mt][0] + lacc[mt][1], l1 = lacc[mt][2] + lacc[mt][3];
        l0 += __shfl_xor_sync(0xFFFFFFFFu, l0, 1);
        l0 += __shfl_xor_sync(0xFFFFFFFFu, l0, 2);
        l1 += __shfl_xor_sync(0xFFFFFFFFu, l1, 1);
        l1 += __shfl_xor_sync(0xFFFFFFFFu, l1, 2);
        const float inv0 = 1.f / l0, inv1 = 1.f / l1;

        const size_t base0 = ((size_t)bB * SEQ + q0 + 32 * w + 16 * mt + r4) * DMODEL
                             + hh * DH;
        const size_t base1 = base0 + (size_t)8 * DMODEL;
        #pragma unroll
        for (int b = 0; b < 5; b++) {
            int d0 = 8 * b + 2 * c4;
            float cs0 = cs_s[d0], cs1 = cs_s[d0 + 1];
            float u0 = (o[mt][b][0] + cs0) * inv0;
            float u1 = (o[mt][b][1] + cs1) * inv0;
            __nv_bfloat16 h0 = __float2bfloat16(u0), h1 = __float2bfloat16(u1);
            *(__nv_bfloat162*)&aoh[base0 + d0] = __nv_bfloat162(h0, h1);
            *(__nv_bfloat162*)&aol[base0 + d0] = __nv_bfloat162(
                __float2bfloat16(u0 - __bfloat162float(h0)),
                __float2bfloat16(u1 - __bfloat162float(h1)));
            float w0 = (o[mt][b][2] + cs0) * inv1;
            float w1 = (o[mt][b][3] + cs1) * inv1;
            __nv_bfloat16 g0 = __float2bfloat16(w0), g1 = __float2bfloat16(w1);
            *(__nv_bfloat162*)&aoh[base1 + d0] = __nv_bfloat162(g0, g1);
            *(__nv_bfloat162*)&aol[base1 + d0] = __nv_bfloat162(
                __float2bfloat16(w0 - __bfloat162float(g0)),
                __float2bfloat16(w1 - __bfloat162float(g1)));
        }
    }
}

// ---------------------------------------------------------------------------
extern "C" void kernel_launch(void* const* d_in, const int* in_sizes, int n_in,
                              void* d_out, int out_size)
{
    const float* x    = (const float*)d_in[0];
    const float* Wq   = (const float*)d_in[1];
    const float* Wk   = (const float*)d_in[2];
    const float* Wv   = (const float*)d_in[3];
    const float* Wout = (const float*)d_in[4];
    const float* bout = (const float*)d_in[5];
    float* out = (float*)d_out;

    __nv_bfloat16 *xh, *xl, *whp, *wlp, *vh, *aoh, *aol, *qt;
    uint32_t* kf;
    float *part;
    cudaGetSymbolAddress((void**)&xh,   g_xh);
    cudaGetSymbolAddress((void**)&xl,   g_xl);
    cudaGetSymbolAddress((void**)&whp,  g_wh);
    cudaGetSymbolAddress((void**)&wlp,  g_wl);
    cudaGetSymbolAddress((void**)&qt,   g_qt);
    cudaGetSymbolAddress((void**)&kf,   g_kf);
    cudaGetSymbolAddress((void**)&vh,   g_vh);
    cudaGetSymbolAddress((void**)&part, g_part);
    cudaGetSymbolAddress((void**)&aoh,  g_aoh);
    cudaGetSymbolAddress((void**)&aol,  g_aol);

    const int WSZ = DMODEL * DMODEL;
    cudaFuncSetAttribute(gemm_qkv, cudaFuncAttributeMaxDynamicSharedMemorySize, 3*ST_BYTES);
    cudaFuncSetAttribute(gemm_out, cudaFuncAttributeMaxDynamicSharedMemorySize, 3*ST_BYTES);
    cudaFuncSetAttribute(attn_kernel, cudaFuncAttributeMaxDynamicSharedMemorySize, SM_ATTN);

    split_kernel<<<(MTOT*DMODEL/4 + 255)/256, 256>>>(x, xh, xl, MTOT*DMODEL/4);
    dim3 gws((WSZ/4 + 255)/256, 4);
    wsplit_kernel<<<gws, 256>>>(Wq, Wk, Wv, Wout, whp, wlp);

    dim3 gqkv(DMODEL / 64, MTOT / 128, 3);   // (5, 64, 3)
    gemm_qkv<<<gqkv, 256, 3*ST_BYTES>>>(xh, xl, whp, wlp, qt, kf, vh, part);

    dim3 gattn(SEQ / 128, NBH);              // (32, 16)
    attn_kernel<<<gattn, 128, SM_ATTN>>>(qt, (const char*)kf, (const char*)vh,
                                         part, aoh, aol);

    dim3 gout(DMODEL / 64, MTOT / 128);      // (5, 64)
    gemm_out<<<gout, 256, 3*ST_BYTES>>>(aoh, aol, whp + 3*WSZ, wlp + 3*WSZ,
                                        bout, out);
}

// round 16
// speedup vs baseline: 1.1020x; 1.0290x over previous
#include <cuda_runtime.h>
#include <cuda_bf16.h>
#include <cstdint>

#define BATCH  2
#define SEQ    4096
#define DMODEL 320
#define HEADS  8
#define DH     40
#define MTOT   (BATCH*SEQ)
#define NBH    (BATCH*HEADS)
#define SCALE  0.15811388300841897f
#define LOG2E  1.4426950408889634f
#define QSCALE (SCALE*LOG2E)
#define NTILE  (SEQ/64)

typedef unsigned long long ull;

// ---- scratch (static device arrays; zero-initialized => padding stays 0) ----
__device__ __nv_bfloat16 g_xh[(size_t)MTOT*DMODEL];
__device__ __nv_bfloat16 g_xl[(size_t)MTOT*DMODEL];
__device__ __nv_bfloat16 g_wh[4][DMODEL*DMODEL];
__device__ __nv_bfloat16 g_wl[4][DMODEL*DMODEL];
__device__ __nv_bfloat16 g_qt[(size_t)NBH*SEQ*48];      // Q*QSCALE bf16, dims 40..47 = 0
__device__ uint32_t      g_kf[(size_t)NBH*NTILE*1280];  // K frag: t01 uint4 | t2 uint1
__device__ __nv_bfloat16 g_vh[(size_t)NBH*DH*SEQ];      // V hi bf16 [bh][d][s]
__device__ float         g_part[64][DMODEL];            // per-m-block exact V colsums
__device__ __nv_bfloat16 g_aoh[(size_t)MTOT*DMODEL];
__device__ __nv_bfloat16 g_aol[(size_t)MTOT*DMODEL];

// ---- helpers ----
__device__ __forceinline__ float ex2f(float x) {
    float y; asm("ex2.approx.ftz.f32 %0, %1;" : "=f"(y) : "f"(x)); return y;
}
__device__ __forceinline__ uint32_t bf16x2(float hi, float lo) {
    uint32_t r; asm("cvt.rn.bf16x2.f32 %0, %1, %2;" : "=r"(r) : "f"(hi), "f"(lo)); return r;
}
__device__ __forceinline__ uint32_t smem_u32(const void* p) {
    uint32_t a;
    asm("{ .reg .u64 t; cvta.to.shared.u64 t, %1; cvt.u32.u64 %0, t; }" : "=r"(a) : "l"(p));
    return a;
}
__device__ __forceinline__ void mma_bf16(float* c, uint32_t a0, uint32_t a1,
                                         uint32_t a2, uint32_t a3, uint32_t b0, uint32_t b1) {
    asm volatile("mma.sync.aligned.m16n8k16.row.col.f32.bf16.bf16.f32 "
        "{%0,%1,%2,%3}, {%4,%5,%6,%7}, {%8,%9}, {%0,%1,%2,%3};"
        : "+f"(c[0]), "+f"(c[1]), "+f"(c[2]), "+f"(c[3])
        : "r"(a0), "r"(a1), "r"(a2), "r"(a3), "r"(b0), "r"(b1));
}
__device__ __forceinline__ void mma_bf16_k8(float* c, uint32_t a0, uint32_t a1,
                                            uint32_t b0) {
    asm volatile("mma.sync.aligned.m16n8k8.row.col.f32.bf16.bf16.f32 "
        "{%0,%1,%2,%3}, {%4,%5}, {%6}, {%0,%1,%2,%3};"
        : "+f"(c[0]), "+f"(c[1]), "+f"(c[2]), "+f"(c[3])
        : "r"(a0), "r"(a1), "r"(b0));
}
__device__ __forceinline__ void ldm4(uint32_t* r, uint32_t addr) {
    asm volatile("ldmatrix.sync.aligned.m8n8.x4.shared.b16 {%0,%1,%2,%3}, [%4];"
        : "=r"(r[0]), "=r"(r[1]), "=r"(r[2]), "=r"(r[3]) : "r"(addr));
}
__device__ __forceinline__ void ldm2(uint32_t* r, uint32_t addr) {
    asm volatile("ldmatrix.sync.aligned.m8n8.x2.shared.b16 {%0,%1}, [%2];"
        : "=r"(r[0]), "=r"(r[1]) : "r"(addr));
}
#define CP16(s, g) asm volatile("cp.async.ca.shared.global [%0], [%1], 16;" :: "r"(s), "l"(g))
#define CP_COMMIT() asm volatile("cp.async.commit_group;" ::: "memory")
#define CP_WAIT(n)  asm volatile("cp.async.wait_group %0;" :: "n"(n) : "memory")

// ---------------------------------------------------------------------------
// fp32 -> bf16 hi/lo splits
// ---------------------------------------------------------------------------
__global__ void __launch_bounds__(256) split_kernel(
    const float* __restrict__ in, __nv_bfloat16* __restrict__ h,
    __nv_bfloat16* __restrict__ l, int n4)
{
    int i = blockIdx.x * 256 + threadIdx.x;
    if (i >= n4) return;
    float4 v = ((const float4*)in)[i];
    __nv_bfloat16 h0 = __float2bfloat16(v.x), h1 = __float2bfloat16(v.y);
    __nv_bfloat16 h2 = __float2bfloat16(v.z), h3 = __float2bfloat16(v.w);
    ((__nv_bfloat162*)h)[2*i]   = __nv_bfloat162(h0, h1);
    ((__nv_bfloat162*)h)[2*i+1] = __nv_bfloat162(h2, h3);
    ((__nv_bfloat162*)l)[2*i]   = __nv_bfloat162(
        __float2bfloat16(v.x - __bfloat162float(h0)),
        __float2bfloat16(v.y - __bfloat162float(h1)));
    ((__nv_bfloat162*)l)[2*i+1] = __nv_bfloat162(
        __float2bfloat16(v.z - __bfloat162float(h2)),
        __float2bfloat16(v.w - __bfloat162float(h3)));
}

__global__ void __launch_bounds__(256) wsplit_kernel(
    const float* __restrict__ w0, const float* __restrict__ w1,
    const float* __restrict__ w2, const float* __restrict__ w3,
    __nv_bfloat16* __restrict__ h, __nv_bfloat16* __restrict__ l)
{
    const int mat = blockIdx.y;
    const float* in = (mat == 0) ? w0 : (mat == 1) ? w1 : (mat == 2) ? w2 : w3;
    int i = blockIdx.x * 256 + threadIdx.x;
    const int n4 = DMODEL * DMODEL / 4;
    if (i >= n4) return;
    float4 v = ((const float4*)in)[i];
    size_t o = (size_t)mat * (DMODEL * DMODEL / 2) + 2 * i;
    __nv_bfloat16 h0 = __float2bfloat16(v.x), h1 = __float2bfloat16(v.y);
    __nv_bfloat16 h2 = __float2bfloat16(v.z), h3 = __float2bfloat16(v.w);
    ((__nv_bfloat162*)h)[o]   = __nv_bfloat162(h0, h1);
    ((__nv_bfloat162*)h)[o+1] = __nv_bfloat162(h2, h3);
    ((__nv_bfloat162*)l)[o]   = __nv_bfloat162(
        __float2bfloat16(v.x - __bfloat162float(h0)),
        __float2bfloat16(v.y - __bfloat162float(h1)));
    ((__nv_bfloat162*)l)[o+1] = __nv_bfloat162(
        __float2bfloat16(v.z - __bfloat162float(h2)),
        __float2bfloat16(v.w - __bfloat162float(h3)));
}

// ---------------------------------------------------------------------------
// GEMM core: BM=128 BN=64 BK=32, 256 thr, 3-stage cp.async, ONE sync per step.
// ---------------------------------------------------------------------------
#define ST_BYTES 30720

struct GemmCore {
    const char* gb[6];
    uint32_t so[6];
    uint32_t a_fb, b_fb;
    float acc[2][4][4];
};

__device__ __forceinline__ void gemm_setup(
    GemmCore& g, int tid, int lane, int wm, int wn, int m0, int n0,
    const __nv_bfloat16* Ah, const __nv_bfloat16* Al,
    const __nv_bfloat16* Wh, const __nv_bfloat16* Wl)
{
    constexpr int K = DMODEL;
    #pragma unroll
    for (int j = 0; j < 6; j++) {
        int c = tid + j * 256;
        if (c < 1024) {
            int split = c >> 9, cc = c & 511, row = cc >> 2, col = cc & 3;
            g.gb[j] = (const char*)((split ? Al : Ah) + (size_t)(m0 + row) * K) + col * 16;
            g.so[j] = split * 10240 + row * 80 + col * 16;
        } else {
            int cc = c - 1024, split = cc >> 8;
            cc &= 255; int row = cc >> 2, col = cc & 3;
            g.gb[j] = (const char*)((split ? Wl : Wh) + (size_t)(n0 + row) * K) + col * 16;
            g.so[j] = 20480 + split * 5120 + row * 80 + col * 16;
        }
    }
    g.a_fb = (wm * 32 + (lane & 15)) * 80 + (lane >> 4) * 16;
    g.b_fb = 20480 + (wn * 32 + (lane & 15)) * 80 + (lane >> 4) * 16;
    #pragma unroll
    for (int mt = 0; mt < 2; mt++)
        #pragma unroll
        for (int nt = 0; nt < 4; nt++)
            #pragma unroll
            for (int i = 0; i < 4; i++) g.acc[mt][nt][i] = 0.f;
}

__device__ __forceinline__ void gemm_main(GemmCore& g, uint32_t sb) {
    constexpr int NKT = DMODEL / 32;   // 10
    #pragma unroll
    for (int p = 0; p < 2; p++) {
        #pragma unroll
        for (int j = 0; j < 6; j++)
            CP16(sb + p * ST_BYTES + g.so[j], g.gb[j] + p * 64);
        CP_COMMIT();
    }

    for (int kt = 0; kt < NKT; kt++) {
        CP_WAIT(1);
        __syncthreads();
        {
            int pre = kt + 2;
            if (pre < NKT) {
                uint32_t stb = sb + (pre % 3) * ST_BYTES;
                #pragma unroll
                for (int j = 0; j < 6; j++)
                    CP16(stb + g.so[j], g.gb[j] + pre * 64);
            }
            CP_COMMIT();
        }

        const uint32_t ah_b = sb + (kt % 3) * ST_BYTES + g.a_fb;
        const uint32_t bh_b = sb + (kt % 3) * ST_BYTES + g.b_fb;
        #pragma unroll
        for (int kk = 0; kk < 2; kk++) {
            uint32_t ah[2][4], al[2][4], bh[2][4], bl[2][4];
            ldm4(ah[0], ah_b + kk * 32);
            ldm4(ah[1], ah_b + 1280 + kk * 32);
            ldm4(al[0], ah_b + 10240 + kk * 32);
            ldm4(al[1], ah_b + 11520 + kk * 32);
            ldm4(bh[0], bh_b + kk * 32);
            ldm4(bh[1], bh_b + 1280 + kk * 32);
            ldm4(bl[0], bh_b + 5120 + kk * 32);
            ldm4(bl[1], bh_b + 6400 + kk * 32);
            #pragma unroll
            for (int mt = 0; mt < 2; mt++)
                #pragma unroll
                for (int gg = 0; gg < 2; gg++)
                    #pragma unroll
                    for (int s = 0; s < 2; s++) {
                        float* c = g.acc[mt][gg * 2 + s];
                        mma_bf16(c, ah[mt][0], ah[mt][1], ah[mt][2], ah[mt][3],
                                 bh[gg][s], bh[gg][s + 2]);
                        mma_bf16(c, ah[mt][0], ah[mt][1], ah[mt][2], ah[mt][3],
                                 bl[gg][s], bl[gg][s + 2]);
                        mma_bf16(c, al[mt][0], al[mt][1], al[mt][2], al[mt][3],
                                 bh[gg][s], bh[gg][s + 2]);
                    }
        }
    }
}

// ---------------------------------------------------------------------------
// Fused QKV projection: blockIdx.z = 0:Q(bf16), 1:K(bf16 frag), 2:V(hi+colsum)
// ---------------------------------------------------------------------------
__global__ void __launch_bounds__(256) gemm_qkv(
    const __nv_bfloat16* __restrict__ Ah, const __nv_bfloat16* __restrict__ Al,
    const __nv_bfloat16* __restrict__ Whb, const __nv_bfloat16* __restrict__ Wlb,
    __nv_bfloat16* __restrict__ Qt, uint32_t* __restrict__ Kf,
    __nv_bfloat16* __restrict__ Vh, float* __restrict__ Part)
{
    extern __shared__ __align__(16) char sm[];
    const int tid = threadIdx.x, lane = tid & 31, w = tid >> 5;
    const int wm = w & 3, wn = w >> 2;
    const int m0 = blockIdx.y * 128, n0 = blockIdx.x * 64;
    const int mode = blockIdx.z;
    const uint32_t sb = smem_u32(sm);

    GemmCore g;
    gemm_setup(g, tid, lane, wm, wn, m0, n0,
               Ah, Al, Whb + (size_t)mode * DMODEL * DMODEL,
               Wlb + (size_t)mode * DMODEL * DMODEL);
    gemm_main(g, sb);

    const int r = lane >> 2, c2 = (lane & 3) * 2;
    #pragma unroll
    for (int mt = 0; mt < 2; mt++) {
        #pragma unroll
        for (int i = 0; i < 2; i++) {
            int m = m0 + wm * 32 + mt * 16 + r + i * 8;
            int b = m >> 12, s = m & (SEQ - 1);
            #pragma unroll
            for (int nt = 0; nt < 4; nt++) {
                float v0 = g.acc[mt][nt][i * 2], v1 = g.acc[mt][nt][i * 2 + 1];
                int n = n0 + wn * 32 + nt * 8 + c2;    // even
                int hd = n / DH, d = n - hd * DH;
                int bh = b * HEADS + hd;
                if (mode == 0) {
                    *(uint32_t*)&Qt[((size_t)bh * SEQ + s) * 48 + d] =
                        bf16x2(v1 * QSCALE, v0 * QSCALE);
                } else if (mode == 1) {
                    int tile = s >> 6, nn = s & 63;
                    int t = d >> 4, rem = d & 15;
                    int reg = rem >> 3, c = (rem >> 1) & 3;
                    size_t base = (size_t)(bh * NTILE + tile) * 1280;
                    if (t < 2)
                        Kf[base + ((nn * 4 + c) << 2) + t * 2 + reg] = bf16x2(v1, v0);
                    else
                        Kf[base + 1024 + nn * 4 + c] = bf16x2(v1, v0);
                } else {
                    size_t o = ((size_t)bh * DH + d) * SEQ + s;
                    Vh[o]       = __float2bfloat16(v0);
                    Vh[o + SEQ] = __float2bfloat16(v1);
                }
            }
        }
    }

    if (mode == 2) {
        __syncthreads();
        float* red = (float*)sm;         // [4][64]
        #pragma unroll
        for (int nt = 0; nt < 4; nt++) {
            float s0 = g.acc[0][nt][0] + g.acc[0][nt][2] + g.acc[1][nt][0] + g.acc[1][nt][2];
            float s1 = g.acc[0][nt][1] + g.acc[0][nt][3] + g.acc[1][nt][1] + g.acc[1][nt][3];
            #pragma unroll
            for (int msk = 4; msk <= 16; msk <<= 1) {
                s0 += __shfl_xor_sync(0xFFFFFFFFu, s0, msk);
                s1 += __shfl_xor_sync(0xFFFFFFFFu, s1, msk);
            }
            if (r == 0) {
                int col = wn * 32 + nt * 8 + c2;
                red[wm * 64 + col]     = s0;
                red[wm * 64 + col + 1] = s1;
            }
        }
        __syncthreads();
        if (tid < 64) {
            Part[(size_t)blockIdx.y * DMODEL + blockIdx.x * 64 + tid] =
                red[tid] + red[64 + tid] + red[128 + tid] + red[192 + tid];
        }
    }
}

// ---------------------------------------------------------------------------
// Out projection (fp32 + bias)
// ---------------------------------------------------------------------------
__global__ void __launch_bounds__(256) gemm_out(
    const __nv_bfloat16* __restrict__ Ah, const __nv_bfloat16* __restrict__ Al,
    const __nv_bfloat16* __restrict__ Wh, const __nv_bfloat16* __restrict__ Wl,
    const float* __restrict__ bias, float* __restrict__ Cf)
{
    extern __shared__ __align__(16) char sm[];
    const int tid = threadIdx.x, lane = tid & 31, w = tid >> 5;
    const int wm = w & 3, wn = w >> 2;
    const int m0 = blockIdx.y * 128, n0 = blockIdx.x * 64;
    const uint32_t sb = smem_u32(sm);

    GemmCore g;
    gemm_setup(g, tid, lane, wm, wn, m0, n0, Ah, Al, Wh, Wl);
    gemm_main(g, sb);

    const int r = lane >> 2, c2 = (lane & 3) * 2;
    #pragma unroll
    for (int mt = 0; mt < 2; mt++) {
        #pragma unroll
        for (int i = 0; i < 2; i++) {
            int m = m0 + wm * 32 + mt * 16 + r + i * 8;
            #pragma unroll
            for (int nt = 0; nt < 4; nt++) {
                int n = n0 + wn * 32 + nt * 8 + c2;
                float2 u = make_float2(g.acc[mt][nt][i*2] + bias[n],
                                       g.acc[mt][nt][i*2+1] + bias[n+1]);
                *(float2*)&Cf[(size_t)m * DMODEL + n] = u;
            }
        }
    }
}

// ---------------------------------------------------------------------------
// Flash attention: cross-tile software pipeline — softmax(i) overlaps the
// tensor drain of MMA1(i+1)/MMA2(i). Same arithmetic (bit-identical output).
// FIX vs R15: mma1_tile takes a BYTE OFFSET; generic-pointer loads use
// smem + offset (R15 wrongly added the cvta'd address to the pointer).
// ---------------------------------------------------------------------------
#define KT_BYTES 5120
#define VROW     144
#define VT_BYTES (DH * VROW)                    // 5760
#define STAGE_BYTES (KT_BYTES + VT_BYTES)       // 10880
#define SM_ATTN (4 * STAGE_BYTES)               // 43520

__global__ void __launch_bounds__(128, 2) attn_kernel(
    const __nv_bfloat16* __restrict__ Qg, const char* __restrict__ Kf,
    const char* __restrict__ Vh, const float* __restrict__ Part,
    __nv_bfloat16* __restrict__ aoh, __nv_bfloat16* __restrict__ aol)
{
    extern __shared__ __align__(16) char smem[];
    __shared__ float cs_s[DH];
    const uint32_t sb = smem_u32(smem);
    const int tid = threadIdx.x, w = tid >> 5, lane = tid & 31;
    const int r4 = lane >> 2, c4 = lane & 3;
    const int bh = blockIdx.y, bB = bh >> 3, hh = bh & 7;
    const int q0 = blockIdx.x * 128;

    // cp.async chunks: K 320 + V 320 = 640 over 128 threads = 5 each
    const char* src[5]; uint32_t doff[5]; int adv[5];
    #pragma unroll
    for (int j = 0; j < 5; j++) {
        int cid = tid + j * 128;
        if (cid < 320) {
            src[j]  = Kf + (size_t)bh * (NTILE * KT_BYTES) + cid * 16;
            adv[j]  = KT_BYTES;
            doff[j] = cid * 16;
        } else {
            int v = cid - 320;
            int d = v >> 3, col = (v & 7) * 16;
            src[j]  = Vh + (((size_t)bh * DH + d) * SEQ) * 2 + col;
            adv[j]  = 128;
            doff[j] = KT_BYTES + d * VROW + col;
        }
    }

    // prologue: prefetch 3 tiles
    #pragma unroll
    for (int p = 0; p < 3; p++) {
        #pragma unroll
        for (int j = 0; j < 5; j++)
            CP16(sb + p * STAGE_BYTES + doff[j], src[j] + (size_t)p * adv[j]);
        CP_COMMIT();
    }

    // exact V colsums for this (bh)
    if (tid < DH) {
        const float* pp = Part + (size_t)(bB * 32) * DMODEL + hh * DH + tid;
        float s = 0.f;
        #pragma unroll
        for (int j = 0; j < 32; j++) s += pp[(size_t)j * DMODEL];
        cs_s[tid] = s;
    }

    // Q A-fragments
    const __nv_bfloat16* Qb = Qg + ((size_t)bh * SEQ + q0) * 48;
    uint32_t qa[2][2][4], qa2[2][2];
    #pragma unroll
    for (int mt = 0; mt < 2; mt++) {
        const int R = 32 * w + 16 * mt + r4;
        #pragma unroll
        for (int t = 0; t < 2; t++) {
            int k0 = 16 * t + 2 * c4;
            qa[mt][t][0] = *(const uint32_t*)(Qb + (size_t)R * 48 + k0);
            qa[mt][t][1] = *(const uint32_t*)(Qb + (size_t)(R + 8) * 48 + k0);
            qa[mt][t][2] = *(const uint32_t*)(Qb + (size_t)R * 48 + k0 + 8);
            qa[mt][t][3] = *(const uint32_t*)(Qb + (size_t)(R + 8) * 48 + k0 + 8);
        }
        int k2 = 32 + 2 * c4;
        qa2[mt][0] = *(const uint32_t*)(Qb + (size_t)R * 48 + k2);
        qa2[mt][1] = *(const uint32_t*)(Qb + (size_t)(R + 8) * 48 + k2);
    }

    const uint32_t vl01 = ((lane & 7) + ((lane >> 4) << 3)) * VROW + ((lane >> 3) & 1) * 16;
    const uint32_t vl4  = (lane & 7) * VROW + ((lane >> 3) & 1) * 16;

    float o[2][5][4];
    #pragma unroll
    for (int mt = 0; mt < 2; mt++)
        #pragma unroll
        for (int b = 0; b < 5; b++) {
            o[mt][b][0]=0.f; o[mt][b][1]=0.f; o[mt][b][2]=0.f; o[mt][b][3]=0.f;
        }
    float lacc[2][4];
    #pragma unroll
    for (int mt = 0; mt < 2; mt++)
        #pragma unroll
        for (int j = 0; j < 4; j++) lacc[mt][j] = 0.f;

    float s[2][8][4];

    // MMA1 for one tile: kofs is a BYTE OFFSET into dynamic smem
    auto mma1_tile = [&](uint32_t kofs) {
        const uint4* kf4     = (const uint4*)(smem + kofs);
        const uint32_t* kf1t = (const uint32_t*)(smem + kofs + 4096);
        #pragma unroll
        for (int mt = 0; mt < 2; mt++)
            #pragma unroll
            for (int b = 0; b < 8; b++) {
                s[mt][b][0]=0.f; s[mt][b][1]=0.f; s[mt][b][2]=0.f; s[mt][b][3]=0.f;
            }
        #pragma unroll
        for (int gq = 0; gq < 2; gq++) {
            uint4 kkA[4];
            #pragma unroll
            for (int b = 0; b < 4; b++)
                kkA[b] = kf4[((8 * (4 * gq + b) + r4) * 4 + c4)];
            #pragma unroll
            for (int b = 0; b < 4; b++)
                #pragma unroll
                for (int mt = 0; mt < 2; mt++)
                    mma_bf16(s[mt][4*gq+b], qa[mt][0][0], qa[mt][0][1],
                             qa[mt][0][2], qa[mt][0][3], kkA[b].x, kkA[b].y);
            #pragma unroll
            for (int b = 0; b < 4; b++)
                #pragma unroll
                for (int mt = 0; mt < 2; mt++)
                    mma_bf16(s[mt][4*gq+b], qa[mt][1][0], qa[mt][1][1],
                             qa[mt][1][2], qa[mt][1][3], kkA[b].z, kkA[b].w);
        }
        uint32_t kkB[8];
        #pragma unroll
        for (int b = 0; b < 8; b++)
            kkB[b] = kf1t[(8 * b + r4) * 4 + c4];
        #pragma unroll
        for (int b = 0; b < 8; b++)
            #pragma unroll
            for (int mt = 0; mt < 2; mt++)
                mma_bf16_k8(s[mt][b], qa2[mt][0], qa2[mt][1], kkB[b]);
    };

    // prologue MMA1 for tile 0
    CP_WAIT(2);
    __syncthreads();
    mma1_tile(0);

    for (int i = 0; i < NTILE; i++) {
        CP_WAIT(1);              // tiles <= i+1 resident
        __syncthreads();
        {
            int pre = i + 3;
            if (pre < NTILE) {
                uint32_t stb = sb + (pre & 3) * STAGE_BYTES;
                #pragma unroll
                for (int j = 0; j < 5; j++)
                    CP16(stb + doff[j], src[j] + (size_t)pre * adv[j]);
            }
            CP_COMMIT();
        }

        // softmax of tile i (s dies here)
        uint32_t pb[2][8][2];
        #pragma unroll
        for (int mt = 0; mt < 2; mt++)
            #pragma unroll
            for (int b = 0; b < 8; b++) {
                float p0 = ex2f(s[mt][b][0]), p1 = ex2f(s[mt][b][1]);
                float p2 = ex2f(s[mt][b][2]), p3 = ex2f(s[mt][b][3]);
                lacc[mt][0] += p0; lacc[mt][1] += p1;
                lacc[mt][2] += p2; lacc[mt][3] += p3;
                pb[mt][b][0] = bf16x2(p1 - 1.f, p0 - 1.f);
                pb[mt][b][1] = bf16x2(p3 - 1.f, p2 - 1.f);
            }

        // MMA1 for tile i+1 (refills s; last iter computes a throwaway on a
        // completed stale slot — never consumed, no race)
        mma1_tile(((i + 1) & 3) * STAGE_BYTES);

        // MMA2 for tile i using pb + V slot i
        const uint32_t vbase = sb + (i & 3) * STAGE_BYTES + KT_BYTES;
        #pragma unroll
        for (int t = 0; t < 4; t++) {
            uint32_t f[10];
            uint32_t hb0 = vbase + 32 * t;
            ldm4(f,     hb0 + vl01);
            ldm4(f + 4, hb0 + 16 * VROW + vl01);
            ldm2(f + 8, hb0 + 32 * VROW + vl4);
            #pragma unroll
            for (int mt = 0; mt < 2; mt++) {
                uint32_t a0 = pb[mt][2*t][0],   a1 = pb[mt][2*t][1];
                uint32_t a2 = pb[mt][2*t+1][0], a3 = pb[mt][2*t+1][1];
                #pragma unroll
                for (int b = 0; b < 5; b++)
                    mma_bf16(o[mt][b], a0, a1, a2, a3, f[2*b], f[2*b+1]);
            }
        }
    }

    // epilogue per m-tile
    #pragma unroll
    for (int mt = 0; mt < 2; mt++) {
        float l0 = lacc[mt][0] + lacc[mt][1], l1 = lacc[mt][2] + lacc[mt][3];
        l0 += __shfl_xor_sync(0xFFFFFFFFu, l0, 1);
        l0 += __shfl_xor_sync(0xFFFFFFFFu, l0, 2);
        l1 += __shfl_xor_sync(0xFFFFFFFFu, l1, 1);
        l1 += __shfl_xor_sync(0xFFFFFFFFu, l1, 2);
        const float inv0 = 1.f / l0, inv1 = 1.f / l1;

        const size_t base0 = ((size_t)bB * SEQ + q0 + 32 * w + 16 * mt + r4) * DMODEL
                             + hh * DH;
        const size_t base1 = base0 + (size_t)8 * DMODEL;
        #pragma unroll
        for (int b = 0; b < 5; b++) {
            int d0 = 8 * b + 2 * c4;
            float cs0 = cs_s[d0], cs1 = cs_s[d0 + 1];
            float u0 = (o[mt][b][0] + cs0) * inv0;
            float u1 = (o[mt][b][1] + cs1) * inv0;
            __nv_bfloat16 h0 = __float2bfloat16(u0), h1 = __float2bfloat16(u1);
            *(__nv_bfloat162*)&aoh[base0 + d0] = __nv_bfloat162(h0, h1);
            *(__nv_bfloat162*)&aol[base0 + d0] = __nv_bfloat162(
                __float2bfloat16(u0 - __bfloat162float(h0)),
                __float2bfloat16(u1 - __bfloat162float(h1)));
            float w0 = (o[mt][b][2] + cs0) * inv1;
            float w1 = (o[mt][b][3] + cs1) * inv1;
            __nv_bfloat16 g0 = __float2bfloat16(w0), g1 = __float2bfloat16(w1);
            *(__nv_bfloat162*)&aoh[base1 + d0] = __nv_bfloat162(g0, g1);
            *(__nv_bfloat162*)&aol[base1 + d0] = __nv_bfloat162(
                __float2bfloat16(w0 - __bfloat162float(g0)),
                __float2bfloat16(w1 - __bfloat162float(g1)));
        }
    }
}

// ---------------------------------------------------------------------------
extern "C" void kernel_launch(void* const* d_in, const int* in_sizes, int n_in,
                              void* d_out, int out_size)
{
    const float* x    = (const float*)d_in[0];
    const float* Wq   = (const float*)d_in[1];
    const float* Wk   = (const float*)d_in[2];
    const float* Wv   = (const float*)d_in[3];
    const float* Wout = (const float*)d_in[4];
    const float* bout = (const float*)d_in[5];
    float* out = (float*)d_out;

    __nv_bfloat16 *xh, *xl, *whp, *wlp, *vh, *aoh, *aol, *qt;
    uint32_t* kf;
    float *part;
    cudaGetSymbolAddress((void**)&xh,   g_xh);
    cudaGetSymbolAddress((void**)&xl,   g_xl);
    cudaGetSymbolAddress((void**)&whp,  g_wh);
    cudaGetSymbolAddress((void**)&wlp,  g_wl);
    cudaGetSymbolAddress((void**)&qt,   g_qt);
    cudaGetSymbolAddress((void**)&kf,   g_kf);
    cudaGetSymbolAddress((void**)&vh,   g_vh);
    cudaGetSymbolAddress((void**)&part, g_part);
    cudaGetSymbolAddress((void**)&aoh,  g_aoh);
    cudaGetSymbolAddress((void**)&aol,  g_aol);

    const int WSZ = DMODEL * DMODEL;
    cudaFuncSetAttribute(gemm_qkv, cudaFuncAttributeMaxDynamicSharedMemorySize, 3*ST_BYTES);
    cudaFuncSetAttribute(gemm_out, cudaFuncAttributeMaxDynamicSharedMemorySize, 3*ST_BYTES);
    cudaFuncSetAttribute(attn_kernel, cudaFuncAttributeMaxDynamicSharedMemorySize, SM_ATTN);

    split_kernel<<<(MTOT*DMODEL/4 + 255)/256, 256>>>(x, xh, xl, MTOT*DMODEL/4);
    dim3 gws((WSZ/4 + 255)/256, 4);
    wsplit_kernel<<<gws, 256>>>(Wq, Wk, Wv, Wout, whp, wlp);

    dim3 gqkv(DMODEL / 64, MTOT / 128, 3);   // (5, 64, 3)
    gemm_qkv<<<gqkv, 256, 3*ST_BYTES>>>(xh, xl, whp, wlp, qt, kf, vh, part);

    dim3 gattn(SEQ / 128, NBH);              // (32, 16)
    attn_kernel<<<gattn, 128, SM_ATTN>>>(qt, (const char*)kf, (const char*)vh,
                                         part, aoh, aol);

    dim3 gout(DMODEL / 64, MTOT / 128);      // (5, 64)
    gemm_out<<<gout, 256, 3*ST_BYTES>>>(aoh, aol, whp + 3*WSZ, wlp + 3*WSZ,
                                        bout, out);
}

// round 17
// speedup vs baseline: 1.1201x; 1.0165x over previous
#include <cuda_runtime.h>
#include <cuda_bf16.h>
#include <cstdint>

#define BATCH  2
#define SEQ    4096
#define DMODEL 320
#define HEADS  8
#define DH     40
#define MTOT   (BATCH*SEQ)
#define NBH    (BATCH*HEADS)
#define SCALE  0.15811388300841897f
#define LOG2E  1.4426950408889634f
#define QSCALE (SCALE*LOG2E)
#define NTILE  (SEQ/64)

typedef unsigned long long ull;

// ---- scratch (static device arrays; zero-initialized => padding stays 0) ----
__device__ __nv_bfloat16 g_xh[(size_t)MTOT*DMODEL];
__device__ __nv_bfloat16 g_xl[(size_t)MTOT*DMODEL];
__device__ __nv_bfloat16 g_wh[4][DMODEL*DMODEL];
__device__ __nv_bfloat16 g_wl[4][DMODEL*DMODEL];
__device__ __nv_bfloat16 g_qt[(size_t)NBH*SEQ*48];      // Q*QSCALE bf16, dims 40..47 = 0
__device__ uint32_t      g_kf[(size_t)NBH*NTILE*1280];  // K frag: t01 uint4 | t2 uint1
__device__ __nv_bfloat16 g_vh[(size_t)NBH*DH*SEQ];      // V hi bf16 [bh][d][s]
__device__ float         g_part[64][DMODEL];            // per-m-block exact V colsums
__device__ __nv_bfloat16 g_aoh[(size_t)MTOT*DMODEL];
__device__ __nv_bfloat16 g_aol[(size_t)MTOT*DMODEL];

// ---- helpers ----
__device__ __forceinline__ float ex2f(float x) {
    float y; asm("ex2.approx.ftz.f32 %0, %1;" : "=f"(y) : "f"(x)); return y;
}
__device__ __forceinline__ uint32_t bf16x2(float hi, float lo) {
    uint32_t r; asm("cvt.rn.bf16x2.f32 %0, %1, %2;" : "=r"(r) : "f"(hi), "f"(lo)); return r;
}
__device__ __forceinline__ uint32_t smem_u32(const void* p) {
    uint32_t a;
    asm("{ .reg .u64 t; cvta.to.shared.u64 t, %1; cvt.u32.u64 %0, t; }" : "=r"(a) : "l"(p));
    return a;
}
__device__ __forceinline__ void mma_bf16(float* c, uint32_t a0, uint32_t a1,
                                         uint32_t a2, uint32_t a3, uint32_t b0, uint32_t b1) {
    asm volatile("mma.sync.aligned.m16n8k16.row.col.f32.bf16.bf16.f32 "
        "{%0,%1,%2,%3}, {%4,%5,%6,%7}, {%8,%9}, {%0,%1,%2,%3};"
        : "+f"(c[0]), "+f"(c[1]), "+f"(c[2]), "+f"(c[3])
        : "r"(a0), "r"(a1), "r"(a2), "r"(a3), "r"(b0), "r"(b1));
}
__device__ __forceinline__ void mma_bf16_k8(float* c, uint32_t a0, uint32_t a1,
                                            uint32_t b0) {
    asm volatile("mma.sync.aligned.m16n8k8.row.col.f32.bf16.bf16.f32 "
        "{%0,%1,%2,%3}, {%4,%5}, {%6}, {%0,%1,%2,%3};"
        : "+f"(c[0]), "+f"(c[1]), "+f"(c[2]), "+f"(c[3])
        : "r"(a0), "r"(a1), "r"(b0));
}
__device__ __forceinline__ void ldm4(uint32_t* r, uint32_t addr) {
    asm volatile("ldmatrix.sync.aligned.m8n8.x4.shared.b16 {%0,%1,%2,%3}, [%4];"
        : "=r"(r[0]), "=r"(r[1]), "=r"(r[2]), "=r"(r[3]) : "r"(addr));
}
__device__ __forceinline__ void ldm2(uint32_t* r, uint32_t addr) {
    asm volatile("ldmatrix.sync.aligned.m8n8.x2.shared.b16 {%0,%1}, [%2];"
        : "=r"(r[0]), "=r"(r[1]) : "r"(addr));
}
#define CP16(s, g) asm volatile("cp.async.ca.shared.global [%0], [%1], 16;" :: "r"(s), "l"(g))
#define CP_COMMIT() asm volatile("cp.async.commit_group;" ::: "memory")
#define CP_WAIT(n)  asm volatile("cp.async.wait_group %0;" :: "n"(n) : "memory")

// ---------------------------------------------------------------------------
// fp32 -> bf16 hi/lo splits
// ---------------------------------------------------------------------------
__global__ void __launch_bounds__(256) split_kernel(
    const float* __restrict__ in, __nv_bfloat16* __restrict__ h,
    __nv_bfloat16* __restrict__ l, int n4)
{
    int i = blockIdx.x * 256 + threadIdx.x;
    if (i >= n4) return;
    float4 v = ((const float4*)in)[i];
    __nv_bfloat16 h0 = __float2bfloat16(v.x), h1 = __float2bfloat16(v.y);
    __nv_bfloat16 h2 = __float2bfloat16(v.z), h3 = __float2bfloat16(v.w);
    ((__nv_bfloat162*)h)[2*i]   = __nv_bfloat162(h0, h1);
    ((__nv_bfloat162*)h)[2*i+1] = __nv_bfloat162(h2, h3);
    ((__nv_bfloat162*)l)[2*i]   = __nv_bfloat162(
        __float2bfloat16(v.x - __bfloat162float(h0)),
        __float2bfloat16(v.y - __bfloat162float(h1)));
    ((__nv_bfloat162*)l)[2*i+1] = __nv_bfloat162(
        __float2bfloat16(v.z - __bfloat162float(h2)),
        __float2bfloat16(v.w - __bfloat162float(h3)));
}

__global__ void __launch_bounds__(256) wsplit_kernel(
    const float* __restrict__ w0, const float* __restrict__ w1,
    const float* __restrict__ w2, const float* __restrict__ w3,
    __nv_bfloat16* __restrict__ h, __nv_bfloat16* __restrict__ l)
{
    const int mat = blockIdx.y;
    const float* in = (mat == 0) ? w0 : (mat == 1) ? w1 : (mat == 2) ? w2 : w3;
    int i = blockIdx.x * 256 + threadIdx.x;
    const int n4 = DMODEL * DMODEL / 4;
    if (i >= n4) return;
    float4 v = ((const float4*)in)[i];
    size_t o = (size_t)mat * (DMODEL * DMODEL / 2) + 2 * i;
    __nv_bfloat16 h0 = __float2bfloat16(v.x), h1 = __float2bfloat16(v.y);
    __nv_bfloat16 h2 = __float2bfloat16(v.z), h3 = __float2bfloat16(v.w);
    ((__nv_bfloat162*)h)[o]   = __nv_bfloat162(h0, h1);
    ((__nv_bfloat162*)h)[o+1] = __nv_bfloat162(h2, h3);
    ((__nv_bfloat162*)l)[o]   = __nv_bfloat162(
        __float2bfloat16(v.x - __bfloat162float(h0)),
        __float2bfloat16(v.y - __bfloat162float(h1)));
    ((__nv_bfloat162*)l)[o+1] = __nv_bfloat162(
        __float2bfloat16(v.z - __bfloat162float(h2)),
        __float2bfloat16(v.w - __bfloat162float(h3)));
}

// ---------------------------------------------------------------------------
// GEMM core: BM=128 BN=64 BK=32, 256 thr, 2-stage cp.async (61KB smem)
// => 3 CTAs/SM with __launch_bounds__(256,3). Same MMA order as before.
// ---------------------------------------------------------------------------
#define ST_BYTES 30720

struct GemmCore {
    const char* gb[6];
    uint32_t so[6];
    uint32_t a_fb, b_fb;
    float acc[2][4][4];
};

__device__ __forceinline__ void gemm_setup(
    GemmCore& g, int tid, int lane, int wm, int wn, int m0, int n0,
    const __nv_bfloat16* Ah, const __nv_bfloat16* Al,
    const __nv_bfloat16* Wh, const __nv_bfloat16* Wl)
{
    constexpr int K = DMODEL;
    #pragma unroll
    for (int j = 0; j < 6; j++) {
        int c = tid + j * 256;
        if (c < 1024) {
            int split = c >> 9, cc = c & 511, row = cc >> 2, col = cc & 3;
            g.gb[j] = (const char*)((split ? Al : Ah) + (size_t)(m0 + row) * K) + col * 16;
            g.so[j] = split * 10240 + row * 80 + col * 16;
        } else {
            int cc = c - 1024, split = cc >> 8;
            cc &= 255; int row = cc >> 2, col = cc & 3;
            g.gb[j] = (const char*)((split ? Wl : Wh) + (size_t)(n0 + row) * K) + col * 16;
            g.so[j] = 20480 + split * 5120 + row * 80 + col * 16;
        }
    }
    g.a_fb = (wm * 32 + (lane & 15)) * 80 + (lane >> 4) * 16;
    g.b_fb = 20480 + (wn * 32 + (lane & 15)) * 80 + (lane >> 4) * 16;
    #pragma unroll
    for (int mt = 0; mt < 2; mt++)
        #pragma unroll
        for (int nt = 0; nt < 4; nt++)
            #pragma unroll
            for (int i = 0; i < 4; i++) g.acc[mt][nt][i] = 0.f;
}

__device__ __forceinline__ void gemm_main(GemmCore& g, uint32_t sb) {
    constexpr int NKT = DMODEL / 32;   // 10
    #pragma unroll
    for (int j = 0; j < 6; j++) CP16(sb + g.so[j], g.gb[j]);
    CP_COMMIT();

    for (int kt = 0; kt < NKT; kt++) {
        const int cur = kt & 1;
        if (kt + 1 < NKT) {
            const uint32_t stb = sb + (cur ^ 1) * ST_BYTES;
            const int gadv = (kt + 1) * 64;
            #pragma unroll
            for (int j = 0; j < 6; j++) CP16(stb + g.so[j], g.gb[j] + gadv);
            CP_COMMIT();
            CP_WAIT(1);
        } else {
            CP_WAIT(0);
        }
        __syncthreads();

        const uint32_t ah_b = sb + cur * ST_BYTES + g.a_fb;
        const uint32_t bh_b = sb + cur * ST_BYTES + g.b_fb;
        #pragma unroll
        for (int kk = 0; kk < 2; kk++) {
            uint32_t ah[2][4], al[2][4], bh[2][4], bl[2][4];
            ldm4(ah[0], ah_b + kk * 32);
            ldm4(ah[1], ah_b + 1280 + kk * 32);
            ldm4(al[0], ah_b + 10240 + kk * 32);
            ldm4(al[1], ah_b + 11520 + kk * 32);
            ldm4(bh[0], bh_b + kk * 32);
            ldm4(bh[1], bh_b + 1280 + kk * 32);
            ldm4(bl[0], bh_b + 5120 + kk * 32);
            ldm4(bl[1], bh_b + 6400 + kk * 32);
            #pragma unroll
            for (int mt = 0; mt < 2; mt++)
                #pragma unroll
                for (int gg = 0; gg < 2; gg++)
                    #pragma unroll
                    for (int s = 0; s < 2; s++) {
                        float* c = g.acc[mt][gg * 2 + s];
                        mma_bf16(c, ah[mt][0], ah[mt][1], ah[mt][2], ah[mt][3],
                                 bh[gg][s], bh[gg][s + 2]);
                        mma_bf16(c, ah[mt][0], ah[mt][1], ah[mt][2], ah[mt][3],
                                 bl[gg][s], bl[gg][s + 2]);
                        mma_bf16(c, al[mt][0], al[mt][1], al[mt][2], al[mt][3],
                                 bh[gg][s], bh[gg][s + 2]);
                    }
        }
        __syncthreads();
    }
}

// ---------------------------------------------------------------------------
// Fused QKV projection: blockIdx.z = 0:Q(bf16), 1:K(bf16 frag), 2:V(hi+colsum)
// ---------------------------------------------------------------------------
__global__ void __launch_bounds__(256, 3) gemm_qkv(
    const __nv_bfloat16* __restrict__ Ah, const __nv_bfloat16* __restrict__ Al,
    const __nv_bfloat16* __restrict__ Whb, const __nv_bfloat16* __restrict__ Wlb,
    __nv_bfloat16* __restrict__ Qt, uint32_t* __restrict__ Kf,
    __nv_bfloat16* __restrict__ Vh, float* __restrict__ Part)
{
    extern __shared__ __align__(16) char sm[];
    const int tid = threadIdx.x, lane = tid & 31, w = tid >> 5;
    const int wm = w & 3, wn = w >> 2;
    const int m0 = blockIdx.y * 128, n0 = blockIdx.x * 64;
    const int mode = blockIdx.z;
    const uint32_t sb = smem_u32(sm);

    GemmCore g;
    gemm_setup(g, tid, lane, wm, wn, m0, n0,
               Ah, Al, Whb + (size_t)mode * DMODEL * DMODEL,
               Wlb + (size_t)mode * DMODEL * DMODEL);
    gemm_main(g, sb);

    const int r = lane >> 2, c2 = (lane & 3) * 2;
    #pragma unroll
    for (int mt = 0; mt < 2; mt++) {
        #pragma unroll
        for (int i = 0; i < 2; i++) {
            int m = m0 + wm * 32 + mt * 16 + r + i * 8;
            int b = m >> 12, s = m & (SEQ - 1);
            #pragma unroll
            for (int nt = 0; nt < 4; nt++) {
                float v0 = g.acc[mt][nt][i * 2], v1 = g.acc[mt][nt][i * 2 + 1];
                int n = n0 + wn * 32 + nt * 8 + c2;    // even
                int hd = n / DH, d = n - hd * DH;
                int bh = b * HEADS + hd;
                if (mode == 0) {
                    *(uint32_t*)&Qt[((size_t)bh * SEQ + s) * 48 + d] =
                        bf16x2(v1 * QSCALE, v0 * QSCALE);
                } else if (mode == 1) {
                    int tile = s >> 6, nn = s & 63;
                    int t = d >> 4, rem = d & 15;
                    int reg = rem >> 3, c = (rem >> 1) & 3;
                    size_t base = (size_t)(bh * NTILE + tile) * 1280;
                    if (t < 2)
                        Kf[base + ((nn * 4 + c) << 2) + t * 2 + reg] = bf16x2(v1, v0);
                    else
                        Kf[base + 1024 + nn * 4 + c] = bf16x2(v1, v0);
                } else {
                    size_t o = ((size_t)bh * DH + d) * SEQ + s;
                    Vh[o]       = __float2bfloat16(v0);
                    Vh[o + SEQ] = __float2bfloat16(v1);
                }
            }
        }
    }

    if (mode == 2) {
        __syncthreads();
        float* red = (float*)sm;         // [4][64]
        #pragma unroll
        for (int nt = 0; nt < 4; nt++) {
            float s0 = g.acc[0][nt][0] + g.acc[0][nt][2] + g.acc[1][nt][0] + g.acc[1][nt][2];
            float s1 = g.acc[0][nt][1] + g.acc[0][nt][3] + g.acc[1][nt][1] + g.acc[1][nt][3];
            #pragma unroll
            for (int msk = 4; msk <= 16; msk <<= 1) {
                s0 += __shfl_xor_sync(0xFFFFFFFFu, s0, msk);
                s1 += __shfl_xor_sync(0xFFFFFFFFu, s1, msk);
            }
            if (r == 0) {
                int col = wn * 32 + nt * 8 + c2;
                red[wm * 64 + col]     = s0;
                red[wm * 64 + col + 1] = s1;
            }
        }
        __syncthreads();
        if (tid < 64) {
            Part[(size_t)blockIdx.y * DMODEL + blockIdx.x * 64 + tid] =
                red[tid] + red[64 + tid] + red[128 + tid] + red[192 + tid];
        }
    }
}

// ---------------------------------------------------------------------------
// Out projection (fp32 + bias)
// ---------------------------------------------------------------------------
__global__ void __launch_bounds__(256, 3) gemm_out(
    const __nv_bfloat16* __restrict__ Ah, const __nv_bfloat16* __restrict__ Al,
    const __nv_bfloat16* __restrict__ Wh, const __nv_bfloat16* __restrict__ Wl,
    const float* __restrict__ bias, float* __restrict__ Cf)
{
    extern __shared__ __align__(16) char sm[];
    const int tid = threadIdx.x, lane = tid & 31, w = tid >> 5;
    const int wm = w & 3, wn = w >> 2;
    const int m0 = blockIdx.y * 128, n0 = blockIdx.x * 64;
    const uint32_t sb = smem_u32(sm);

    GemmCore g;
    gemm_setup(g, tid, lane, wm, wn, m0, n0, Ah, Al, Wh, Wl);
    gemm_main(g, sb);

    const int r = lane >> 2, c2 = (lane & 3) * 2;
    #pragma unroll
    for (int mt = 0; mt < 2; mt++) {
        #pragma unroll
        for (int i = 0; i < 2; i++) {
            int m = m0 + wm * 32 + mt * 16 + r + i * 8;
            #pragma unroll
            for (int nt = 0; nt < 4; nt++) {
                int n = n0 + wn * 32 + nt * 8 + c2;
                float2 u = make_float2(g.acc[mt][nt][i*2] + bias[n],
                                       g.acc[mt][nt][i*2+1] + bias[n+1]);
                *(float2*)&Cf[(size_t)m * DMODEL + n] = u;
            }
        }
    }
}

// ---------------------------------------------------------------------------
// Flash attention: cross-tile software pipeline (unchanged from R16).
// ---------------------------------------------------------------------------
#define KT_BYTES 5120
#define VROW     144
#define VT_BYTES (DH * VROW)                    // 5760
#define STAGE_BYTES (KT_BYTES + VT_BYTES)       // 10880
#define SM_ATTN (4 * STAGE_BYTES)               // 43520

__global__ void __launch_bounds__(128, 2) attn_kernel(
    const __nv_bfloat16* __restrict__ Qg, const char* __restrict__ Kf,
    const char* __restrict__ Vh, const float* __restrict__ Part,
    __nv_bfloat16* __restrict__ aoh, __nv_bfloat16* __restrict__ aol)
{
    extern __shared__ __align__(16) char smem[];
    __shared__ float cs_s[DH];
    const uint32_t sb = smem_u32(smem);
    const int tid = threadIdx.x, w = tid >> 5, lane = tid & 31;
    const int r4 = lane >> 2, c4 = lane & 3;
    const int bh = blockIdx.y, bB = bh >> 3, hh = bh & 7;
    const int q0 = blockIdx.x * 128;

    const char* src[5]; uint32_t doff[5]; int adv[5];
    #pragma unroll
    for (int j = 0; j < 5; j++) {
        int cid = tid + j * 128;
        if (cid < 320) {
            src[j]  = Kf + (size_t)bh * (NTILE * KT_BYTES) + cid * 16;
            adv[j]  = KT_BYTES;
            doff[j] = cid * 16;
        } else {
            int v = cid - 320;
            int d = v >> 3, col = (v & 7) * 16;
            src[j]  = Vh + (((size_t)bh * DH + d) * SEQ) * 2 + col;
            adv[j]  = 128;
            doff[j] = KT_BYTES + d * VROW + col;
        }
    }

    #pragma unroll
    for (int p = 0; p < 3; p++) {
        #pragma unroll
        for (int j = 0; j < 5; j++)
            CP16(sb + p * STAGE_BYTES + doff[j], src[j] + (size_t)p * adv[j]);
        CP_COMMIT();
    }

    if (tid < DH) {
        const float* pp = Part + (size_t)(bB * 32) * DMODEL + hh * DH + tid;
        float s = 0.f;
        #pragma unroll
        for (int j = 0; j < 32; j++) s += pp[(size_t)j * DMODEL];
        cs_s[tid] = s;
    }

    const __nv_bfloat16* Qb = Qg + ((size_t)bh * SEQ + q0) * 48;
    uint32_t qa[2][2][4], qa2[2][2];
    #pragma unroll
    for (int mt = 0; mt < 2; mt++) {
        const int R = 32 * w + 16 * mt + r4;
        #pragma unroll
        for (int t = 0; t < 2; t++) {
            int k0 = 16 * t + 2 * c4;
            qa[mt][t][0] = *(const uint32_t*)(Qb + (size_t)R * 48 + k0);
            qa[mt][t][1] = *(const uint32_t*)(Qb + (size_t)(R + 8) * 48 + k0);
            qa[mt][t][2] = *(const uint32_t*)(Qb + (size_t)R * 48 + k0 + 8);
            qa[mt][t][3] = *(const uint32_t*)(Qb + (size_t)(R + 8) * 48 + k0 + 8);
        }
        int k2 = 32 + 2 * c4;
        qa2[mt][0] = *(const uint32_t*)(Qb + (size_t)R * 48 + k2);
        qa2[mt][1] = *(const uint32_t*)(Qb + (size_t)(R + 8) * 48 + k2);
    }

    const uint32_t vl01 = ((lane & 7) + ((lane >> 4) << 3)) * VROW + ((lane >> 3) & 1) * 16;
    const uint32_t vl4  = (lane & 7) * VROW + ((lane >> 3) & 1) * 16;

    float o[2][5][4];
    #pragma unroll
    for (int mt = 0; mt < 2; mt++)
        #pragma unroll
        for (int b = 0; b < 5; b++) {
            o[mt][b][0]=0.f; o[mt][b][1]=0.f; o[mt][b][2]=0.f; o[mt][b][3]=0.f;
        }
    float lacc[2][4];
    #pragma unroll
    for (int mt = 0; mt < 2; mt++)
        #pragma unroll
        for (int j = 0; j < 4; j++) lacc[mt][j] = 0.f;

    float s[2][8][4];

    auto mma1_tile = [&](uint32_t kofs) {
        const uint4* kf4     = (const uint4*)(smem + kofs);
        const uint32_t* kf1t = (const uint32_t*)(smem + kofs + 4096);
        #pragma unroll
        for (int mt = 0; mt < 2; mt++)
            #pragma unroll
            for (int b = 0; b < 8; b++) {
                s[mt][b][0]=0.f; s[mt][b][1]=0.f; s[mt][b][2]=0.f; s[mt][b][3]=0.f;
            }
        #pragma unroll
        for (int gq = 0; gq < 2; gq++) {
            uint4 kkA[4];
            #pragma unroll
            for (int b = 0; b < 4; b++)
                kkA[b] = kf4[((8 * (4 * gq + b) + r4) * 4 + c4)];
            #pragma unroll
            for (int b = 0; b < 4; b++)
                #pragma unroll
                for (int mt = 0; mt < 2; mt++)
                    mma_bf16(s[mt][4*gq+b], qa[mt][0][0], qa[mt][0][1],
                             qa[mt][0][2], qa[mt][0][3], kkA[b].x, kkA[b].y);
            #pragma unroll
            for (int b = 0; b < 4; b++)
                #pragma unroll
                for (int mt = 0; mt < 2; mt++)
                    mma_bf16(s[mt][4*gq+b], qa[mt][1][0], qa[mt][1][1],
                             qa[mt][1][2], qa[mt][1][3], kkA[b].z, kkA[b].w);
        }
        uint32_t kkB[8];
        #pragma unroll
        for (int b = 0; b < 8; b++)
            kkB[b] = kf1t[(8 * b + r4) * 4 + c4];
        #pragma unroll
        for (int b = 0; b < 8; b++)
            #pragma unroll
            for (int mt = 0; mt < 2; mt++)
                mma_bf16_k8(s[mt][b], qa2[mt][0], qa2[mt][1], kkB[b]);
    };

    CP_WAIT(2);
    __syncthreads();
    mma1_tile(0);

    for (int i = 0; i < NTILE; i++) {
        CP_WAIT(1);
        __syncthreads();
        {
            int pre = i + 3;
            if (pre < NTILE) {
                uint32_t stb = sb + (pre & 3) * STAGE_BYTES;
                #pragma unroll
                for (int j = 0; j < 5; j++)
                    CP16(stb + doff[j], src[j] + (size_t)pre * adv[j]);
            }
            CP_COMMIT();
        }

        uint32_t pb[2][8][2];
        #pragma unroll
        for (int mt = 0; mt < 2; mt++)
            #pragma unroll
            for (int b = 0; b < 8; b++) {
                float p0 = ex2f(s[mt][b][0]), p1 = ex2f(s[mt][b][1]);
                float p2 = ex2f(s[mt][b][2]), p3 = ex2f(s[mt][b][3]);
                lacc[mt][0] += p0; lacc[mt][1] += p1;
                lacc[mt][2] += p2; lacc[mt][3] += p3;
                pb[mt][b][0] = bf16x2(p1 - 1.f, p0 - 1.f);
                pb[mt][b][1] = bf16x2(p3 - 1.f, p2 - 1.f);
            }

        mma1_tile(((i + 1) & 3) * STAGE_BYTES);

        const uint32_t vbase = sb + (i & 3) * STAGE_BYTES + KT_BYTES;
        #pragma unroll
        for (int t = 0; t < 4; t++) {
            uint32_t f[10];
            uint32_t hb0 = vbase + 32 * t;
            ldm4(f,     hb0 + vl01);
            ldm4(f + 4, hb0 + 16 * VROW + vl01);
            ldm2(f + 8, hb0 + 32 * VROW + vl4);
            #pragma unroll
            for (int mt = 0; mt < 2; mt++) {
                uint32_t a0 = pb[mt][2*t][0],   a1 = pb[mt][2*t][1];
                uint32_t a2 = pb[mt][2*t+1][0], a3 = pb[mt][2*t+1][1];
                #pragma unroll
                for (int b = 0; b < 5; b++)
                    mma_bf16(o[mt][b], a0, a1, a2, a3, f[2*b], f[2*b+1]);
            }
        }
    }

    #pragma unroll
    for (int mt = 0; mt < 2; mt++) {
        float l0 = lacc[mt][0] + lacc[mt][1], l1 = lacc[mt][2] + lacc[mt][3];
        l0 += __shfl_xor_sync(0xFFFFFFFFu, l0, 1);
        l0 += __shfl_xor_sync(0xFFFFFFFFu, l0, 2);
        l1 += __shfl_xor_sync(0xFFFFFFFFu, l1, 1);
        l1 += __shfl_xor_sync(0xFFFFFFFFu, l1, 2);
        const float inv0 = 1.f / l0, inv1 = 1.f / l1;

        const size_t base0 = ((size_t)bB * SEQ + q0 + 32 * w + 16 * mt + r4) * DMODEL
                             + hh * DH;
        const size_t base1 = base0 + (size_t)8 * DMODEL;
        #pragma unroll
        for (int b = 0; b < 5; b++) {
            int d0 = 8 * b + 2 * c4;
            float cs0 = cs_s[d0], cs1 = cs_s[d0 + 1];
            float u0 = (o[mt][b][0] + cs0) * inv0;
            float u1 = (o[mt][b][1] + cs1) * inv0;
            __nv_bfloat16 h0 = __float2bfloat16(u0), h1 = __float2bfloat16(u1);
            *(__nv_bfloat162*)&aoh[base0 + d0] = __nv_bfloat162(h0, h1);
            *(__nv_bfloat162*)&aol[base0 + d0] = __nv_bfloat162(
                __float2bfloat16(u0 - __bfloat162float(h0)),
                __float2bfloat16(u1 - __bfloat162float(h1)));
            float w0 = (o[mt][b][2] + cs0) * inv1;
            float w1 = (o[mt][b][3] + cs1) * inv1;
            __nv_bfloat16 g0 = __float2bfloat16(w0), g1 = __float2bfloat16(w1);
            *(__nv_bfloat162*)&aoh[base1 + d0] = __nv_bfloat162(g0, g1);
            *(__nv_bfloat162*)&aol[base1 + d0] = __nv_bfloat162(
                __float2bfloat16(w0 - __bfloat162float(g0)),
                __float2bfloat16(w1 - __bfloat162float(g1)));
        }
    }
}

// ---------------------------------------------------------------------------
extern "C" void kernel_launch(void* const* d_in, const int* in_sizes, int n_in,
                              void* d_out, int out_size)
{
    const float* x    = (const float*)d_in[0];
    const float* Wq   = (const float*)d_in[1];
    const float* Wk   = (const float*)d_in[2];
    const float* Wv   = (const float*)d_in[3];
    const float* Wout = (const float*)d_in[4];
    const float* bout = (const float*)d_in[5];
    float* out = (float*)d_out;

    __nv_bfloat16 *xh, *xl, *whp, *wlp, *vh, *aoh, *aol, *qt;
    uint32_t* kf;
    float *part;
    cudaGetSymbolAddress((void**)&xh,   g_xh);
    cudaGetSymbolAddress((void**)&xl,   g_xl);
    cudaGetSymbolAddress((void**)&whp,  g_wh);
    cudaGetSymbolAddress((void**)&wlp,  g_wl);
    cudaGetSymbolAddress((void**)&qt,   g_qt);
    cudaGetSymbolAddress((void**)&kf,   g_kf);
    cudaGetSymbolAddress((void**)&vh,   g_vh);
    cudaGetSymbolAddress((void**)&part, g_part);
    cudaGetSymbolAddress((void**)&aoh,  g_aoh);
    cudaGetSymbolAddress((void**)&aol,  g_aol);

    const int WSZ = DMODEL * DMODEL;
    cudaFuncSetAttribute(gemm_qkv, cudaFuncAttributeMaxDynamicSharedMemorySize, 2*ST_BYTES);
    cudaFuncSetAttribute(gemm_out, cudaFuncAttributeMaxDynamicSharedMemorySize, 2*ST_BYTES);
    cudaFuncSetAttribute(attn_kernel, cudaFuncAttributeMaxDynamicSharedMemorySize, SM_ATTN);

    split_kernel<<<(MTOT*DMODEL/4 + 255)/256, 256>>>(x, xh, xl, MTOT*DMODEL/4);
    dim3 gws((WSZ/4 + 255)/256, 4);
    wsplit_kernel<<<gws, 256>>>(Wq, Wk, Wv, Wout, whp, wlp);

    dim3 gqkv(DMODEL / 64, MTOT / 128, 3);   // (5, 64, 3)
    gemm_qkv<<<gqkv, 256, 2*ST_BYTES>>>(xh, xl, whp, wlp, qt, kf, vh, part);

    dim3 gattn(SEQ / 128, NBH);              // (32, 16)
    attn_kernel<<<gattn, 128, SM_ATTN>>>(qt, (const char*)kf, (const char*)vh,
                                         part, aoh, aol);

    dim3 gout(DMODEL / 64, MTOT / 128);      // (5, 64)
    gemm_out<<<gout, 256, 2*ST_BYTES>>>(aoh, aol, whp + 3*WSZ, wlp + 3*WSZ,
                                        bout, out);
}